// round 9
// baseline (speedup 1.0000x reference)
#include <cuda_runtime.h>

#define N   128
#define N3  (N*N*N)

// BU BV BW U1 V1 W1 B R0 P1 (9 x N3) + Rp1(64^3) + Rp2(32^3) + Rp3(16^3) + W16(16^3)
__device__ float g_scratch[9 * (size_t)N3 + 262144 + 32768 + 2 * 4096];

static __device__ __forceinline__ int cl(int x) { return x < 0 ? 0 : (x > N - 1 ? N - 1 : x); }
static __device__ __forceinline__ int ix(int d, int h, int w) { return (d << 14) + (h << 7) + w; }

static __device__ __forceinline__ float4 ld4(const float* __restrict__ p, int i) {
    return *reinterpret_cast<const float4*>(p + i);
}
static __device__ __forceinline__ void st4(float* __restrict__ p, int i, float4 v) {
    *reinterpret_cast<float4*>(p + i) = v;
}
static __device__ __forceinline__ float4 operator+(float4 a, float4 b) { return make_float4(a.x+b.x, a.y+b.y, a.z+b.z, a.w+b.w); }
static __device__ __forceinline__ float4 operator-(float4 a, float4 b) { return make_float4(a.x-b.x, a.y-b.y, a.z-b.z, a.w-b.w); }
static __device__ __forceinline__ float4 operator*(float s, float4 a) { return make_float4(s*a.x, s*a.y, s*a.z, s*a.w); }
static __device__ __forceinline__ float4 operator*(float4 a, float4 b) { return make_float4(a.x*b.x, a.y*b.y, a.z*b.z, a.w*b.w); }

struct S7 { float4 c, n, s, b, t; float wl, wr; };

static __device__ __forceinline__ S7 ld7(const float* __restrict__ A,
                                         int cb, int nb, int sb, int bb, int tb, int w4) {
    S7 r;
    r.c = ld4(A, cb); r.n = ld4(A, nb); r.s = ld4(A, sb); r.b = ld4(A, bb); r.t = ld4(A, tb);
    r.wl = (w4 > 0)   ? A[cb - 1] : r.c.x;
    r.wr = (w4 < 124) ? A[cb + 4] : r.c.w;
    return r;
}
static __device__ __forceinline__ float4 westv(const S7& s) { return make_float4(s.wl, s.c.x, s.c.y, s.c.z); }
static __device__ __forceinline__ float4 eastv(const S7& s) { return make_float4(s.c.y, s.c.z, s.c.w, s.wr); }

static __device__ __forceinline__ float4 rcp4(float dt, float4 g) {
    return make_float4(1.f/(1.f+dt*g.x), 1.f/(1.f+dt*g.y), 1.f/(1.f+dt*g.z), 1.f/(1.f+dt*g.w));
}
static __device__ __forceinline__ void scale7(S7& u, const S7& f) {
    u.c = u.c * f.c; u.n = u.n * f.n; u.s = u.s * f.s; u.b = u.b * f.b; u.t = u.t * f.t;
    u.wl *= f.wl; u.wr *= f.wr;
}

#define IDX6(dd)                                      \
    const int d = (dd);                               \
    const int dB = cl(d - 1), dT = cl(d + 1);         \
    const int cb = ix(d, h, w4);                      \
    const int nb = ix(d, hN, w4), sb = ix(d, hS, w4); \
    const int bb = ix(dB, h, w4), tb = ix(dT, h, w4);

// ---------------------------------------------------------------------------
__global__ void __launch_bounds__(128) k_predictor(
    const float* __restrict__ U, const float* __restrict__ V, const float* __restrict__ W_,
    const float* __restrict__ P, const float* __restrict__ SG, const float* __restrict__ DT,
    float* __restrict__ BU, float* __restrict__ BV, float* __restrict__ BW)
{
    const int w4 = threadIdx.x << 2;
    const int h  = (blockIdx.y << 2) + threadIdx.y;
    const int hS = cl(h - 1), hN = cl(h + 1);
    IDX6(blockIdx.z);

    S7 g  = ld7(SG, cb, nb, sb, bb, tb, w4);
    S7 p  = ld7(P,  cb, nb, sb, bb, tb, w4);
    S7 su = ld7(U,  cb, nb, sb, bb, tb, w4);
    S7 sv = ld7(V,  cb, nb, sb, bb, tb, w4);
    S7 sw = ld7(W_, cb, nb, sb, bb, tb, w4);
    const float dt = DT[0];

    S7 f;
    f.c = rcp4(dt, g.c); f.n = rcp4(dt, g.n); f.s = rcp4(dt, g.s);
    f.b = rcp4(dt, g.b); f.t = rcp4(dt, g.t);
    f.wl = 1.f/(1.f+dt*g.wl); f.wr = 1.f/(1.f+dt*g.wr);

    scale7(su, f); scale7(sv, f); scale7(sw, f);
    const float4 uc = su.c, vc = sv.c, wc = sw.c;

    float4 gpx = 0.5f * (eastv(p) - westv(p));
    float4 gpy = 0.5f * (p.n - p.s);
    float4 gpz = 0.5f * (p.t - p.b);

    {
        float4 west = westv(su); if (w4 == 0) west.x = 1.0f;
        float4 east = eastv(su);
        float4 lap = west + east + su.n + su.s + su.b + su.t - 6.f * su.c;
        float4 ax = 0.5f * (east - west), ay = 0.5f * (su.n - su.s), az = 0.5f * (su.t - su.b);
        st4(BU, cb, (uc + 0.5f*dt*(lap - uc*ax - vc*ay - wc*az) - dt*gpx) * f.c);
    }
    {
        float4 west = westv(sv), east = eastv(sv);
        float4 lap = west + east + sv.n + sv.s + sv.b + sv.t - 6.f * sv.c;
        float4 ax = 0.5f * (east - west), ay = 0.5f * (sv.n - sv.s), az = 0.5f * (sv.t - sv.b);
        st4(BV, cb, (vc + 0.5f*dt*(lap - uc*ax - vc*ay - wc*az) - dt*gpy) * f.c);
    }
    {
        float4 west = westv(sw), east = eastv(sw);
        float4 lap = west + east + sw.n + sw.s + sw.b + sw.t - 6.f * sw.c;
        float4 ax = 0.5f * (east - west), ay = 0.5f * (sw.n - sw.s), az = 0.5f * (sw.t - sw.b);
        st4(BW, cb, (wc + 0.5f*dt*(lap - uc*ax - vc*ay - wc*az) - dt*gpz) * f.c);
    }
}

// ---------------------------------------------------------------------------
__global__ void __launch_bounds__(128) k_corrector(
    const float* __restrict__ BU, const float* __restrict__ BV, const float* __restrict__ BW,
    const float* __restrict__ U, const float* __restrict__ V, const float* __restrict__ W_,
    const float* __restrict__ P, const float* __restrict__ SG, const float* __restrict__ DT,
    float* __restrict__ U1, float* __restrict__ V1, float* __restrict__ W1)
{
    const int w4 = threadIdx.x << 2;
    const int h  = (blockIdx.y << 2) + threadIdx.y;
    const int hS = cl(h - 1), hN = cl(h + 1);
    IDX6(blockIdx.z);

    const float4 sg = ld4(SG, cb);
    const float4 Uc = ld4(U, cb), Vc = ld4(V, cb), Wc = ld4(W_, cb);
    S7 p = ld7(P,  cb, nb, sb, bb, tb, w4);
    S7 a = ld7(BU, cb, nb, sb, bb, tb, w4);
    S7 b = ld7(BV, cb, nb, sb, bb, tb, w4);
    S7 c = ld7(BW, cb, nb, sb, bb, tb, w4);
    const float dt = DT[0];

    const float4 fc = rcp4(dt, sg);
    const float4 uc = Uc * fc, vc = Vc * fc, wc = Wc * fc;
    const float4 buc = a.c, bvc = b.c, bwc = c.c;

    float4 gpx = 0.5f * (eastv(p) - westv(p));
    float4 gpy = 0.5f * (p.n - p.s);
    float4 gpz = 0.5f * (p.t - p.b);

    {
        float4 west = westv(a); if (w4 == 0) west.x = 1.0f;
        float4 east = eastv(a);
        float4 lap = west + east + a.n + a.s + a.b + a.t - 6.f * a.c;
        float4 ax = 0.5f * (east - west), ay = 0.5f * (a.n - a.s), az = 0.5f * (a.t - a.b);
        st4(U1, cb, (uc + dt*(lap - buc*ax - bvc*ay - bwc*az) - dt*gpx) * fc);
    }
    {
        float4 west = westv(b), east = eastv(b);
        float4 lap = west + east + b.n + b.s + b.b + b.t - 6.f * b.c;
        float4 ax = 0.5f * (east - west), ay = 0.5f * (b.n - b.s), az = 0.5f * (b.t - b.b);
        st4(V1, cb, (vc + dt*(lap - buc*ax - bvc*ay - bwc*az) - dt*gpy) * fc);
    }
    {
        float4 west = westv(c), east = eastv(c);
        float4 lap = west + east + c.n + c.s + c.b + c.t - 6.f * c.c;
        float4 ax = 0.5f * (east - west), ay = 0.5f * (c.n - c.s), az = 0.5f * (c.t - c.b);
        st4(W1, cb, (wc + dt*(lap - buc*ax - bvc*ay - bwc*az) - dt*gpz) * fc);
    }
}

// ---------------------------------------------------------------------------
__global__ void __launch_bounds__(256) k_residdiv(
    const float* __restrict__ P, const float* __restrict__ U1,
    const float* __restrict__ V1, const float* __restrict__ W1,
    const float* __restrict__ DT,
    float* __restrict__ B, float* __restrict__ R0, float* __restrict__ Rp1)
{
    __shared__ float sred[8][64];
    const int w4 = threadIdx.x << 2;
    const int h  = (blockIdx.y << 3) + threadIdx.y;
    const int hS = cl(h - 1), hN = cl(h + 1);

    S7 pp[2]; float4 u1c[2], vn[2], vs[2], wb[2], wt[2];
    float uwl[2], uwr[2]; int cbs[2];

    #pragma unroll
    for (int d2 = 0; d2 < 2; ++d2) {
        IDX6((blockIdx.z << 1) + d2);
        cbs[d2] = cb;
        pp[d2]  = ld7(P, cb, nb, sb, bb, tb, w4);
        u1c[d2] = ld4(U1, cb);
        uwl[d2] = (w4 > 0)   ? U1[cb - 1] : u1c[d2].x;
        uwr[d2] = (w4 < 124) ? U1[cb + 4] : u1c[d2].w;
        vn[d2] = ld4(V1, nb); vs[d2] = ld4(V1, sb);
        wt[d2] = ld4(W1, tb); wb[d2] = ld4(W1, bb);
    }
    const float dt = DT[0];
    const float rdt = -1.f / dt;

    float acc0 = 0.f, acc1 = 0.f;
    #pragma unroll
    for (int d2 = 0; d2 < 2; ++d2) {
        float wl = uwl[d2]; if (w4 == 0) wl = 1.0f;
        float4 west = make_float4(wl, u1c[d2].x, u1c[d2].y, u1c[d2].z);
        float4 east = make_float4(u1c[d2].y, u1c[d2].z, u1c[d2].w, uwr[d2]);
        float4 b4 = rdt * (0.5f*(east - west) + 0.5f*(vn[d2] - vs[d2]) + 0.5f*(wt[d2] - wb[d2]));
        st4(B, cbs[d2], b4);

        float4 pw = westv(pp[d2]), pe = eastv(pp[d2]);
        float4 lap = pw + pe + pp[d2].n + pp[d2].s + pp[d2].b + pp[d2].t - 6.f * pp[d2].c;
        float4 rr = lap - b4;
        st4(R0, cbs[d2], rr);
        acc0 += rr.x + rr.y;
        acc1 += rr.z + rr.w;
    }
    sred[threadIdx.y][threadIdx.x * 2]     = acc0;
    sred[threadIdx.y][threadIdx.x * 2 + 1] = acc1;
    __syncthreads();
    int tid = threadIdx.y * 32 + threadIdx.x;
    int cw = tid & 63, chh = tid >> 6;
    float v = sred[2 * chh][cw] + sred[2 * chh + 1][cw];
    int dc = blockIdx.z, hc = (blockIdx.y << 2) + chh;
    Rp1[(dc * 64 + hc) * 64 + cw] = 0.125f * v;
}

// ---------------------------------------------------------------------------
__global__ void __launch_bounds__(256) k_resid(
    const float* __restrict__ P, const float* __restrict__ B,
    float* __restrict__ R0, float* __restrict__ Rp1)
{
    __shared__ float sred[8][64];
    const int w4 = threadIdx.x << 2;
    const int h  = (blockIdx.y << 3) + threadIdx.y;
    const int hS = cl(h - 1), hN = cl(h + 1);

    S7 pp[2]; float4 bc[2]; int cbs[2];
    #pragma unroll
    for (int d2 = 0; d2 < 2; ++d2) {
        IDX6((blockIdx.z << 1) + d2);
        cbs[d2] = cb;
        pp[d2] = ld7(P, cb, nb, sb, bb, tb, w4);
        bc[d2] = ld4(B, cb);
    }
    float acc0 = 0.f, acc1 = 0.f;
    #pragma unroll
    for (int d2 = 0; d2 < 2; ++d2) {
        float4 pw = westv(pp[d2]), pe = eastv(pp[d2]);
        float4 lap = pw + pe + pp[d2].n + pp[d2].s + pp[d2].b + pp[d2].t - 6.f * pp[d2].c;
        float4 rr = lap - bc[d2];
        st4(R0, cbs[d2], rr);
        acc0 += rr.x + rr.y;
        acc1 += rr.z + rr.w;
    }
    sred[threadIdx.y][threadIdx.x * 2]     = acc0;
    sred[threadIdx.y][threadIdx.x * 2 + 1] = acc1;
    __syncthreads();
    int tid = threadIdx.y * 32 + threadIdx.x;
    int cw = tid & 63, chh = tid >> 6;
    float v = sred[2 * chh][cw] + sred[2 * chh + 1][cw];
    int dc = blockIdx.z, hc = (blockIdx.y << 2) + chh;
    Rp1[(dc * 64 + hc) * 64 + cw] = 0.125f * v;
}

// ---------------------------------------------------------------------------
// Two-level restriction 64^3 -> 32^3 AND 16^3; one 16^3 tile per block,
// float4 loads (4 per thread, MLP=4). 64 blocks x 256 threads.
// ---------------------------------------------------------------------------
__global__ void __launch_bounds__(256) k_restrict2(
    const float* __restrict__ Rp1, float* __restrict__ Rp2, float* __restrict__ Rp3)
{
    __shared__ float s[4096];   // 16^3
    __shared__ float s2[512];   // 8^3
    const int tid = threadIdx.x;
    const int bw = blockIdx.x & 3, bh = (blockIdx.x >> 2) & 3, bd = blockIdx.x >> 4;

    // load one 16-float row per thread as 4 float4s
    {
        const int lh = tid & 15, ld = tid >> 4;
        const int gd = bd * 16 + ld, gh = bh * 16 + lh, gw0 = bw * 16;
        const int gbase = (gd * 64 + gh) * 64 + gw0;
        float4 r0 = ld4(Rp1, gbase), r1 = ld4(Rp1, gbase + 4);
        float4 r2 = ld4(Rp1, gbase + 8), r3 = ld4(Rp1, gbase + 12);
        float* srow = s + (ld * 16 + lh) * 16;
        *reinterpret_cast<float4*>(srow)      = r0;
        *reinterpret_cast<float4*>(srow + 4)  = r1;
        *reinterpret_cast<float4*>(srow + 8)  = r2;
        *reinterpret_cast<float4*>(srow + 12) = r3;
    }
    __syncthreads();
    // 16 -> 8 (512 cells, 2 per thread)
    #pragma unroll
    for (int k = tid; k < 512; k += 256) {
        int cw = k & 7, chh = (k >> 3) & 7, cd = k >> 6;
        int b0 = ((cd * 2) * 16 + chh * 2) * 16 + cw * 2;
        float v = 0.125f * (s[b0] + s[b0+1] + s[b0+16] + s[b0+17]
                          + s[b0+256] + s[b0+257] + s[b0+272] + s[b0+273]);
        s2[k] = v;
        Rp2[((bd*8+cd) * 32 + (bh*8+chh)) * 32 + (bw*8+cw)] = v;
    }
    __syncthreads();
    // 8 -> 4 (64 cells)
    if (tid < 64) {
        int cw = tid & 3, chh = (tid >> 2) & 3, cd = tid >> 4;
        int b0 = ((cd * 2) * 8 + chh * 2) * 8 + cw * 2;
        float v = 0.125f * (s2[b0] + s2[b0+1] + s2[b0+8] + s2[b0+9]
                          + s2[b0+64] + s2[b0+65] + s2[b0+72] + s2[b0+73]);
        Rp3[((bd*4+cd) * 16 + (bh*4+chh)) * 16 + (bw*4+cw)] = v;
    }
}

static __device__ __forceinline__ float mgcell(const float* __restrict__ Wp, int mc,
                                               float r, int d, int h, int w, int m)
{
    auto g = [&](int dd, int hh, int ww) -> float {
        if (dd < 0 || dd >= m || hh < 0 || hh >= m || ww < 0 || ww >= m) return 0.f;
        return Wp[((dd >> 1) * mc + (hh >> 1)) * mc + (ww >> 1)];
    };
    float wc = g(d, h, w);
    float lap = g(d-1,h,w) + g(d+1,h,w) + g(d,h-1,w) + g(d,h+1,w) + g(d,h,w-1) + g(d,h,w+1) - 6.f * wc;
    return wc - lap / (-6.f) + r / (-6.f);
}

// ---------------------------------------------------------------------------
// Single-block coarse solver on 16^3: restrict 16->8->4->2->1, solve up to W16.
// ---------------------------------------------------------------------------
__global__ void __launch_bounds__(512) k_coarse16(
    const float* __restrict__ R16g, float* __restrict__ W16g, float* __restrict__ o_r)
{
    __shared__ float R16[4096], R8[512], R4[64], R2[8];
    __shared__ float W8[512], W4[64], W2[8], W1a[1];
    const int tid = threadIdx.x;

    #pragma unroll
    for (int k = tid; k < 4096; k += 512) R16[k] = R16g[k];
    __syncthreads();
    {
        int w = tid & 7, h = (tid >> 3) & 7, d = tid >> 6;
        int b0 = ((2 * d) * 16 + 2 * h) * 16 + 2 * w;
        R8[tid] = 0.125f * (R16[b0] + R16[b0+1] + R16[b0+16] + R16[b0+17]
                          + R16[b0+256] + R16[b0+257] + R16[b0+272] + R16[b0+273]);
    }
    __syncthreads();
    if (tid < 64) {
        int w = tid & 3, h = (tid >> 2) & 3, d = tid >> 4;
        int b0 = ((2 * d) * 8 + 2 * h) * 8 + 2 * w;
        R4[tid] = 0.125f * (R8[b0] + R8[b0+1] + R8[b0+8] + R8[b0+9]
                          + R8[b0+64] + R8[b0+65] + R8[b0+72] + R8[b0+73]);
    }
    __syncthreads();
    if (tid < 8) {
        int w = tid & 1, h = (tid >> 1) & 1, d = tid >> 2;
        int b0 = ((2 * d) * 4 + 2 * h) * 4 + 2 * w;
        R2[tid] = 0.125f * (R4[b0] + R4[b0+1] + R4[b0+4] + R4[b0+5]
                          + R4[b0+16] + R4[b0+17] + R4[b0+20] + R4[b0+21]);
    }
    __syncthreads();
    if (tid == 0) {
        float r1 = 0.125f * (R2[0]+R2[1]+R2[2]+R2[3]+R2[4]+R2[5]+R2[6]+R2[7]);
        W1a[0] = r1 / (-6.f);
        if (o_r) o_r[0] = r1;
    }
    __syncthreads();
    if (tid < 8) {
        int w = tid & 1, h = (tid >> 1) & 1, d = tid >> 2;
        W2[tid] = mgcell(W1a, 1, R2[tid], d, h, w, 2);
    }
    __syncthreads();
    if (tid < 64) {
        int w = tid & 3, h = (tid >> 2) & 3, d = tid >> 4;
        W4[tid] = mgcell(W2, 2, R4[tid], d, h, w, 4);
    }
    __syncthreads();
    {
        int w = tid & 7, h = (tid >> 3) & 7, d = tid >> 6;
        W8[tid] = mgcell(W4, 4, R8[tid], d, h, w, 8);
    }
    __syncthreads();
    #pragma unroll
    for (int k = tid; k < 4096; k += 512) {
        int w = k & 15, h = (k >> 4) & 15, d = k >> 8;
        W16g[k] = mgcell(W8, 8, R16[k], d, h, w, 16);
    }
}

// ---------------------------------------------------------------------------
// p-update with BOTH m=32 and m=64 MG levels fused.
// Per-block W32 slab (3 x 4 x 32) computed in smem from W16 + Rp2.
// ---------------------------------------------------------------------------
__global__ void __launch_bounds__(256) k_pupdate(
    const float* __restrict__ pold, const float* __restrict__ W16,
    const float* __restrict__ Rp2, const float* __restrict__ Rp1,
    const float* __restrict__ r0,
    float* __restrict__ pnew, float* __restrict__ wmg_out)
{
    __shared__ float slab[384];   // [di:3][hi:4][w32:32]
    const int d  = blockIdx.z;
    const int hb = blockIdx.y;
    const int d64c = d >> 1;
    const int d32base = (d64c >> 1) - 1;
    const int h32base = (hb << 1) - 1;

    const int tid = threadIdx.y * 32 + threadIdx.x;
    for (int i = tid; i < 384; i += 256) {
        const int w32 = i & 31, hi = (i >> 5) & 3, di = i >> 7;
        const int d32 = d32base + di, h32 = h32base + hi;
        float v = 0.f;
        if (d32 >= 0 && d32 < 32 && h32 >= 0 && h32 < 32)
            v = mgcell(W16, 16, Rp2[(d32 * 32 + h32) * 32 + w32], d32, h32, w32, 32);
        slab[i] = v;
    }
    __syncthreads();

    const int w4 = threadIdx.x << 2;
    const int h  = (hb << 3) + threadIdx.y;
    const int cb = ix(d, h, w4);
    const int h64 = h >> 1;
    const int cw0 = w4 >> 1;

    auto g64 = [&](int dd, int hh, int ww) -> float {
        if (dd < 0 || dd >= 64 || hh < 0 || hh >= 64 || ww < 0 || ww >= 64) return 0.f;
        return slab[(((dd >> 1) - d32base) * 4 + ((hh >> 1) - h32base)) * 32 + (ww >> 1)];
    };
    auto mg64 = [&](float r, int ww) -> float {
        float wc = g64(d64c, h64, ww);
        float lap = g64(d64c - 1, h64, ww) + g64(d64c + 1, h64, ww)
                  + g64(d64c, h64 - 1, ww) + g64(d64c, h64 + 1, ww)
                  + g64(d64c, h64, ww - 1) + g64(d64c, h64, ww + 1) - 6.f * wc;
        return wc - lap / (-6.f) + r / (-6.f);
    };

    const int crow = (d64c * 64 + h64) * 64 + cw0;
    const float r64_0 = Rp1[crow], r64_1 = Rp1[crow + 1];
    const float4 r4 = ld4(r0, cb);
    const float4 po = ld4(pold, cb);

    const float mg0 = mg64(r64_0, cw0);
    const float mg1 = mg64(r64_1, cw0 + 1);
    const float4 wv = make_float4(mg0, mg0, mg1, mg1);
    const float4 pn = po - wv - make_float4(r4.x/(-6.f), r4.y/(-6.f), r4.z/(-6.f), r4.w/(-6.f));
    st4(pnew, cb, pn);
    if (wmg_out) st4(wmg_out, cb, wv);
}

// ---------------------------------------------------------------------------
__global__ void __launch_bounds__(256) k_final(
    const float* __restrict__ U1, const float* __restrict__ V1, const float* __restrict__ W1,
    const float* __restrict__ Pf, const float* __restrict__ SG, const float* __restrict__ DT,
    float* __restrict__ OU, float* __restrict__ OV, float* __restrict__ OW)
{
    const int w4 = threadIdx.x << 2;
    const int h  = (blockIdx.y << 3) + threadIdx.y;
    const int hS = cl(h - 1), hN = cl(h + 1);
    IDX6(blockIdx.z);

    S7 p = ld7(Pf, cb, nb, sb, bb, tb, w4);
    const float4 sg = ld4(SG, cb);
    const float4 u1 = ld4(U1, cb), v1 = ld4(V1, cb), w1 = ld4(W1, cb);
    const float dt = DT[0];

    const float4 fc = rcp4(dt, sg);
    float4 gpx = 0.5f * (eastv(p) - westv(p));
    float4 gpy = 0.5f * (p.n - p.s);
    float4 gpz = 0.5f * (p.t - p.b);
    st4(OU, cb, (u1 - dt * gpx) * fc);
    st4(OV, cb, (v1 - dt * gpy) * fc);
    st4(OW, cb, (w1 - dt * gpz) * fc);
}

// ---------------------------------------------------------------------------
extern "C" void kernel_launch(void* const* d_in, const int* in_sizes, int n_in,
                              void* d_out, int out_size)
{
    const float* U  = (const float*)d_in[0];
    const float* V  = (const float*)d_in[1];
    const float* W_ = (const float*)d_in[2];
    const float* P  = (const float*)d_in[3];
    const float* SG = (const float*)d_in[4];
    const float* DT = (const float*)d_in[5];

    float* out   = (float*)d_out;
    float* o_u   = out;
    float* o_v   = out + (size_t)N3;
    float* o_w   = out + 2 * (size_t)N3;
    float* o_p   = out + 3 * (size_t)N3;
    float* o_wmg = out + 4 * (size_t)N3;
    float* o_r   = out + 5 * (size_t)N3;

    float* S = nullptr;
    cudaGetSymbolAddress((void**)&S, g_scratch);
    float* BU = S;
    float* BV = S + (size_t)N3;
    float* BW = S + 2 * (size_t)N3;
    float* U1 = S + 3 * (size_t)N3;
    float* V1 = S + 4 * (size_t)N3;
    float* W1 = S + 5 * (size_t)N3;
    float* B  = S + 6 * (size_t)N3;
    float* R0 = S + 7 * (size_t)N3;
    float* P1 = S + 8 * (size_t)N3;
    float* Rp1 = S + 9 * (size_t)N3;     // 64^3
    float* Rp2 = Rp1 + 262144;           // 32^3
    float* Rp3 = Rp2 + 32768;            // 16^3
    float* W16 = Rp3 + 4096;             // 16^3

    dim3 blkF(32, 4), grdF(1, 32, 128);     // fat kernels, 128 thr
    dim3 blkR(32, 8), grdR(1, 16, 64);      // residual (2 planes/block)
    dim3 grdP(1, 16, 128);                  // full-depth grids with blkR

    k_predictor<<<grdF, blkF>>>(U, V, W_, P, SG, DT, BU, BV, BW);
    k_corrector<<<grdF, blkF>>>(BU, BV, BW, U, V, W_, P, SG, DT, U1, V1, W1);

    // iteration 0 (div fused into residual)
    k_residdiv<<<grdR, blkR>>>(P, U1, V1, W1, DT, B, R0, Rp1);
    k_restrict2<<<64, 256>>>(Rp1, Rp2, Rp3);
    k_coarse16<<<1, 512>>>(Rp3, W16, nullptr);
    k_pupdate<<<grdP, blkR>>>(P, W16, Rp2, Rp1, R0, P1, nullptr);

    // iteration 1
    k_resid<<<grdR, blkR>>>(P1, B, R0, Rp1);
    k_restrict2<<<64, 256>>>(Rp1, Rp2, Rp3);
    k_coarse16<<<1, 512>>>(Rp3, W16, o_r);
    k_pupdate<<<grdP, blkR>>>(P1, W16, Rp2, Rp1, R0, o_p, o_wmg);

    k_final<<<grdP, blkR>>>(U1, V1, W1, o_p, SG, DT, o_u, o_v, o_w);
}

// round 10
// speedup vs baseline: 1.0265x; 1.0265x over previous
#include <cuda_runtime.h>

#define N   128
#define N3  (N*N*N)

// BU BV BW U1 V1 W1 B R0 P1 (9 x N3) + Rp1(64^3) + Rp2(32^3) + W32(32^3) + W16(16^3)
__device__ float g_scratch[9 * (size_t)N3 + 262144 + 2 * 32768 + 4096];

static __device__ __forceinline__ int cl(int x) { return x < 0 ? 0 : (x > N - 1 ? N - 1 : x); }
static __device__ __forceinline__ int ix(int d, int h, int w) { return (d << 14) + (h << 7) + w; }

static __device__ __forceinline__ float4 ld4(const float* __restrict__ p, int i) {
    return *reinterpret_cast<const float4*>(p + i);
}
static __device__ __forceinline__ void st4(float* __restrict__ p, int i, float4 v) {
    *reinterpret_cast<float4*>(p + i) = v;
}
static __device__ __forceinline__ float4 operator+(float4 a, float4 b) { return make_float4(a.x+b.x, a.y+b.y, a.z+b.z, a.w+b.w); }
static __device__ __forceinline__ float4 operator-(float4 a, float4 b) { return make_float4(a.x-b.x, a.y-b.y, a.z-b.z, a.w-b.w); }
static __device__ __forceinline__ float4 operator*(float s, float4 a) { return make_float4(s*a.x, s*a.y, s*a.z, s*a.w); }
static __device__ __forceinline__ float4 operator*(float4 a, float4 b) { return make_float4(a.x*b.x, a.y*b.y, a.z*b.z, a.w*b.w); }

struct S7 { float4 c, n, s, b, t; float wl, wr; };

static __device__ __forceinline__ S7 ld7(const float* __restrict__ A,
                                         int cb, int nb, int sb, int bb, int tb, int w4) {
    S7 r;
    r.c = ld4(A, cb); r.n = ld4(A, nb); r.s = ld4(A, sb); r.b = ld4(A, bb); r.t = ld4(A, tb);
    r.wl = (w4 > 0)   ? A[cb - 1] : r.c.x;
    r.wr = (w4 < 124) ? A[cb + 4] : r.c.w;
    return r;
}
static __device__ __forceinline__ float4 westv(const S7& s) { return make_float4(s.wl, s.c.x, s.c.y, s.c.z); }
static __device__ __forceinline__ float4 eastv(const S7& s) { return make_float4(s.c.y, s.c.z, s.c.w, s.wr); }

static __device__ __forceinline__ float4 rcp4(float dt, float4 g) {
    return make_float4(1.f/(1.f+dt*g.x), 1.f/(1.f+dt*g.y), 1.f/(1.f+dt*g.z), 1.f/(1.f+dt*g.w));
}
static __device__ __forceinline__ void scale7(S7& u, const S7& f) {
    u.c = u.c * f.c; u.n = u.n * f.n; u.s = u.s * f.s; u.b = u.b * f.b; u.t = u.t * f.t;
    u.wl *= f.wl; u.wr *= f.wr;
}

#define IDX6(dd)                                      \
    const int d = (dd);                               \
    const int dB = cl(d - 1), dT = cl(d + 1);         \
    const int cb = ix(d, h, w4);                      \
    const int nb = ix(d, hN, w4), sb = ix(d, hS, w4); \
    const int bb = ix(dB, h, w4), tb = ix(dT, h, w4);

// ---------------------------------------------------------------------------
__global__ void __launch_bounds__(128) k_predictor(
    const float* __restrict__ U, const float* __restrict__ V, const float* __restrict__ W_,
    const float* __restrict__ P, const float* __restrict__ SG, const float* __restrict__ DT,
    float* __restrict__ BU, float* __restrict__ BV, float* __restrict__ BW)
{
    const int w4 = threadIdx.x << 2;
    const int h  = (blockIdx.y << 2) + threadIdx.y;
    const int hS = cl(h - 1), hN = cl(h + 1);
    IDX6(blockIdx.z);

    S7 g  = ld7(SG, cb, nb, sb, bb, tb, w4);
    S7 p  = ld7(P,  cb, nb, sb, bb, tb, w4);
    S7 su = ld7(U,  cb, nb, sb, bb, tb, w4);
    S7 sv = ld7(V,  cb, nb, sb, bb, tb, w4);
    S7 sw = ld7(W_, cb, nb, sb, bb, tb, w4);
    const float dt = DT[0];

    S7 f;
    f.c = rcp4(dt, g.c); f.n = rcp4(dt, g.n); f.s = rcp4(dt, g.s);
    f.b = rcp4(dt, g.b); f.t = rcp4(dt, g.t);
    f.wl = 1.f/(1.f+dt*g.wl); f.wr = 1.f/(1.f+dt*g.wr);

    scale7(su, f); scale7(sv, f); scale7(sw, f);
    const float4 uc = su.c, vc = sv.c, wc = sw.c;

    float4 gpx = 0.5f * (eastv(p) - westv(p));
    float4 gpy = 0.5f * (p.n - p.s);
    float4 gpz = 0.5f * (p.t - p.b);

    {
        float4 west = westv(su); if (w4 == 0) west.x = 1.0f;
        float4 east = eastv(su);
        float4 lap = west + east + su.n + su.s + su.b + su.t - 6.f * su.c;
        float4 ax = 0.5f * (east - west), ay = 0.5f * (su.n - su.s), az = 0.5f * (su.t - su.b);
        st4(BU, cb, (uc + 0.5f*dt*(lap - uc*ax - vc*ay - wc*az) - dt*gpx) * f.c);
    }
    {
        float4 west = westv(sv), east = eastv(sv);
        float4 lap = west + east + sv.n + sv.s + sv.b + sv.t - 6.f * sv.c;
        float4 ax = 0.5f * (east - west), ay = 0.5f * (sv.n - sv.s), az = 0.5f * (sv.t - sv.b);
        st4(BV, cb, (vc + 0.5f*dt*(lap - uc*ax - vc*ay - wc*az) - dt*gpy) * f.c);
    }
    {
        float4 west = westv(sw), east = eastv(sw);
        float4 lap = west + east + sw.n + sw.s + sw.b + sw.t - 6.f * sw.c;
        float4 ax = 0.5f * (east - west), ay = 0.5f * (sw.n - sw.s), az = 0.5f * (sw.t - sw.b);
        st4(BW, cb, (wc + 0.5f*dt*(lap - uc*ax - vc*ay - wc*az) - dt*gpz) * f.c);
    }
}

// ---------------------------------------------------------------------------
__global__ void __launch_bounds__(128) k_corrector(
    const float* __restrict__ BU, const float* __restrict__ BV, const float* __restrict__ BW,
    const float* __restrict__ U, const float* __restrict__ V, const float* __restrict__ W_,
    const float* __restrict__ P, const float* __restrict__ SG, const float* __restrict__ DT,
    float* __restrict__ U1, float* __restrict__ V1, float* __restrict__ W1)
{
    const int w4 = threadIdx.x << 2;
    const int h  = (blockIdx.y << 2) + threadIdx.y;
    const int hS = cl(h - 1), hN = cl(h + 1);
    IDX6(blockIdx.z);

    const float4 sg = ld4(SG, cb);
    const float4 Uc = ld4(U, cb), Vc = ld4(V, cb), Wc = ld4(W_, cb);
    S7 p = ld7(P,  cb, nb, sb, bb, tb, w4);
    S7 a = ld7(BU, cb, nb, sb, bb, tb, w4);
    S7 b = ld7(BV, cb, nb, sb, bb, tb, w4);
    S7 c = ld7(BW, cb, nb, sb, bb, tb, w4);
    const float dt = DT[0];

    const float4 fc = rcp4(dt, sg);
    const float4 uc = Uc * fc, vc = Vc * fc, wc = Wc * fc;
    const float4 buc = a.c, bvc = b.c, bwc = c.c;

    float4 gpx = 0.5f * (eastv(p) - westv(p));
    float4 gpy = 0.5f * (p.n - p.s);
    float4 gpz = 0.5f * (p.t - p.b);

    {
        float4 west = westv(a); if (w4 == 0) west.x = 1.0f;
        float4 east = eastv(a);
        float4 lap = west + east + a.n + a.s + a.b + a.t - 6.f * a.c;
        float4 ax = 0.5f * (east - west), ay = 0.5f * (a.n - a.s), az = 0.5f * (a.t - a.b);
        st4(U1, cb, (uc + dt*(lap - buc*ax - bvc*ay - bwc*az) - dt*gpx) * fc);
    }
    {
        float4 west = westv(b), east = eastv(b);
        float4 lap = west + east + b.n + b.s + b.b + b.t - 6.f * b.c;
        float4 ax = 0.5f * (east - west), ay = 0.5f * (b.n - b.s), az = 0.5f * (b.t - b.b);
        st4(V1, cb, (vc + dt*(lap - buc*ax - bvc*ay - bwc*az) - dt*gpy) * fc);
    }
    {
        float4 west = westv(c), east = eastv(c);
        float4 lap = west + east + c.n + c.s + c.b + c.t - 6.f * c.c;
        float4 ax = 0.5f * (east - west), ay = 0.5f * (c.n - c.s), az = 0.5f * (c.t - c.b);
        st4(W1, cb, (wc + dt*(lap - buc*ax - bvc*ay - bwc*az) - dt*gpz) * fc);
    }
}

// ---------------------------------------------------------------------------
// Iter-0 fused: div + residual + 128->64 restriction + 64->32 restriction.
// Block covers 4 d-planes (2 pair-passes), h:8, w:128. Grid (1,16,32).
// ---------------------------------------------------------------------------
__global__ void __launch_bounds__(256) k_residdiv(
    const float* __restrict__ P, const float* __restrict__ U1,
    const float* __restrict__ V1, const float* __restrict__ W1,
    const float* __restrict__ DT,
    float* __restrict__ B, float* __restrict__ R0,
    float* __restrict__ Rp1, float* __restrict__ Rp2)
{
    __shared__ float sred[8][64];
    __shared__ float c64buf[2][4][64];
    const int w4 = threadIdx.x << 2;
    const int h  = (blockIdx.y << 3) + threadIdx.y;
    const int hS = cl(h - 1), hN = cl(h + 1);
    const int tid = threadIdx.y * 32 + threadIdx.x;
    const float dt = DT[0];
    const float rdt = -1.f / dt;

    #pragma unroll
    for (int pair = 0; pair < 2; ++pair) {
        S7 pp[2]; float4 u1c[2], vn[2], vs[2], wb[2], wt[2];
        float uwl[2], uwr[2]; int cbs[2];
        #pragma unroll
        for (int d2 = 0; d2 < 2; ++d2) {
            IDX6((blockIdx.z << 2) + (pair << 1) + d2);
            cbs[d2] = cb;
            pp[d2]  = ld7(P, cb, nb, sb, bb, tb, w4);
            u1c[d2] = ld4(U1, cb);
            uwl[d2] = (w4 > 0)   ? U1[cb - 1] : u1c[d2].x;
            uwr[d2] = (w4 < 124) ? U1[cb + 4] : u1c[d2].w;
            vn[d2] = ld4(V1, nb); vs[d2] = ld4(V1, sb);
            wt[d2] = ld4(W1, tb); wb[d2] = ld4(W1, bb);
        }
        float acc0 = 0.f, acc1 = 0.f;
        #pragma unroll
        for (int d2 = 0; d2 < 2; ++d2) {
            float wl = uwl[d2]; if (w4 == 0) wl = 1.0f;
            float4 west = make_float4(wl, u1c[d2].x, u1c[d2].y, u1c[d2].z);
            float4 east = make_float4(u1c[d2].y, u1c[d2].z, u1c[d2].w, uwr[d2]);
            float4 b4 = rdt * (0.5f*(east - west) + 0.5f*(vn[d2] - vs[d2]) + 0.5f*(wt[d2] - wb[d2]));
            st4(B, cbs[d2], b4);

            float4 pw = westv(pp[d2]), pe = eastv(pp[d2]);
            float4 lap = pw + pe + pp[d2].n + pp[d2].s + pp[d2].b + pp[d2].t - 6.f * pp[d2].c;
            float4 rr = lap - b4;
            st4(R0, cbs[d2], rr);
            acc0 += rr.x + rr.y;
            acc1 += rr.z + rr.w;
        }
        sred[threadIdx.y][threadIdx.x * 2]     = acc0;
        sred[threadIdx.y][threadIdx.x * 2 + 1] = acc1;
        __syncthreads();
        {
            int cw = tid & 63, chh = tid >> 6;
            float v = 0.125f * (sred[2 * chh][cw] + sred[2 * chh + 1][cw]);
            int dc = (blockIdx.z << 1) + pair, hc = (blockIdx.y << 2) + chh;
            Rp1[(dc * 64 + hc) * 64 + cw] = v;
            c64buf[pair][chh][cw] = v;
        }
        __syncthreads();
    }
    if (tid < 64) {
        int wc2 = tid & 31, hc2 = tid >> 5;
        float s = 0.f;
        #pragma unroll
        for (int dc = 0; dc < 2; ++dc)
            #pragma unroll
            for (int hh = 0; hh < 2; ++hh)
                s += c64buf[dc][hc2 * 2 + hh][wc2 * 2] + c64buf[dc][hc2 * 2 + hh][wc2 * 2 + 1];
        Rp2[((blockIdx.z) * 32 + (blockIdx.y << 1) + hc2) * 32 + wc2] = 0.125f * s;
    }
}

// ---------------------------------------------------------------------------
// Iter-1 residual: r0 = lap(p) - B, + 128->64 + 64->32 restrictions.
// ---------------------------------------------------------------------------
__global__ void __launch_bounds__(256) k_resid(
    const float* __restrict__ P, const float* __restrict__ B,
    float* __restrict__ R0, float* __restrict__ Rp1, float* __restrict__ Rp2)
{
    __shared__ float sred[8][64];
    __shared__ float c64buf[2][4][64];
    const int w4 = threadIdx.x << 2;
    const int h  = (blockIdx.y << 3) + threadIdx.y;
    const int hS = cl(h - 1), hN = cl(h + 1);
    const int tid = threadIdx.y * 32 + threadIdx.x;

    #pragma unroll
    for (int pair = 0; pair < 2; ++pair) {
        S7 pp[2]; float4 bc[2]; int cbs[2];
        #pragma unroll
        for (int d2 = 0; d2 < 2; ++d2) {
            IDX6((blockIdx.z << 2) + (pair << 1) + d2);
            cbs[d2] = cb;
            pp[d2] = ld7(P, cb, nb, sb, bb, tb, w4);
            bc[d2] = ld4(B, cb);
        }
        float acc0 = 0.f, acc1 = 0.f;
        #pragma unroll
        for (int d2 = 0; d2 < 2; ++d2) {
            float4 pw = westv(pp[d2]), pe = eastv(pp[d2]);
            float4 lap = pw + pe + pp[d2].n + pp[d2].s + pp[d2].b + pp[d2].t - 6.f * pp[d2].c;
            float4 rr = lap - bc[d2];
            st4(R0, cbs[d2], rr);
            acc0 += rr.x + rr.y;
            acc1 += rr.z + rr.w;
        }
        sred[threadIdx.y][threadIdx.x * 2]     = acc0;
        sred[threadIdx.y][threadIdx.x * 2 + 1] = acc1;
        __syncthreads();
        {
            int cw = tid & 63, chh = tid >> 6;
            float v = 0.125f * (sred[2 * chh][cw] + sred[2 * chh + 1][cw]);
            int dc = (blockIdx.z << 1) + pair, hc = (blockIdx.y << 2) + chh;
            Rp1[(dc * 64 + hc) * 64 + cw] = v;
            c64buf[pair][chh][cw] = v;
        }
        __syncthreads();
    }
    if (tid < 64) {
        int wc2 = tid & 31, hc2 = tid >> 5;
        float s = 0.f;
        #pragma unroll
        for (int dc = 0; dc < 2; ++dc)
            #pragma unroll
            for (int hh = 0; hh < 2; ++hh)
                s += c64buf[dc][hc2 * 2 + hh][wc2 * 2] + c64buf[dc][hc2 * 2 + hh][wc2 * 2 + 1];
        Rp2[((blockIdx.z) * 32 + (blockIdx.y << 1) + hc2) * 32 + wc2] = 0.125f * s;
    }
}

static __device__ __forceinline__ float mgcell(const float* __restrict__ Wp, int mc,
                                               float r, int d, int h, int w, int m)
{
    auto g = [&](int dd, int hh, int ww) -> float {
        if (dd < 0 || dd >= m || hh < 0 || hh >= m || ww < 0 || ww >= m) return 0.f;
        return Wp[((dd >> 1) * mc + (hh >> 1)) * mc + (ww >> 1)];
    };
    float wc = g(d, h, w);
    float lap = g(d-1,h,w) + g(d+1,h,w) + g(d,h-1,w) + g(d,h+1,w) + g(d,h,w-1) + g(d,h,w+1) - 6.f * wc;
    return wc - lap / (-6.f) + r / (-6.f);
}

// ---------------------------------------------------------------------------
// Single-block coarse solver: 32^3 -> 16^3 restriction (float4 global reads),
// then 16->8->4->2->1 and solve back up to W16.
// ---------------------------------------------------------------------------
__global__ void __launch_bounds__(512) k_coarse16(
    const float* __restrict__ Rp2g, float* __restrict__ W16g, float* __restrict__ o_r)
{
    __shared__ float R16[4096], R8[512], R4[64], R2[8];
    __shared__ float W8[512], W4[64], W2[8], W1a[1];
    const int tid = threadIdx.x;

    // 32 -> 16: 2 threads per (d16,h16) row; each handles 8 c16 cells.
    {
        const int r = tid >> 1, halfw = tid & 1;   // r 0..255
        const int d16 = r >> 4, h16 = r & 15;
        const int w0 = halfw * 8;                  // c16 w cells [w0, w0+8)
        const int fb = ((2 * d16) * 32 + 2 * h16) * 32 + 2 * w0;
        float a[16], b[16], c[16], e[16];
        #pragma unroll
        for (int q = 0; q < 4; ++q) {
            *reinterpret_cast<float4*>(a + 4*q) = ld4(Rp2g, fb + 4*q);
            *reinterpret_cast<float4*>(b + 4*q) = ld4(Rp2g, fb + 32 + 4*q);
            *reinterpret_cast<float4*>(c + 4*q) = ld4(Rp2g, fb + 1024 + 4*q);
            *reinterpret_cast<float4*>(e + 4*q) = ld4(Rp2g, fb + 1056 + 4*q);
        }
        #pragma unroll
        for (int k = 0; k < 8; ++k) {
            R16[(d16 * 16 + h16) * 16 + w0 + k] =
                0.125f * (a[2*k] + a[2*k+1] + b[2*k] + b[2*k+1]
                        + c[2*k] + c[2*k+1] + e[2*k] + e[2*k+1]);
        }
    }
    __syncthreads();
    {   // 16 -> 8
        int w = tid & 7, h = (tid >> 3) & 7, d = tid >> 6;
        int b0 = ((2 * d) * 16 + 2 * h) * 16 + 2 * w;
        R8[tid] = 0.125f * (R16[b0] + R16[b0+1] + R16[b0+16] + R16[b0+17]
                          + R16[b0+256] + R16[b0+257] + R16[b0+272] + R16[b0+273]);
    }
    __syncthreads();
    if (tid < 64) {
        int w = tid & 3, h = (tid >> 2) & 3, d = tid >> 4;
        int b0 = ((2 * d) * 8 + 2 * h) * 8 + 2 * w;
        R4[tid] = 0.125f * (R8[b0] + R8[b0+1] + R8[b0+8] + R8[b0+9]
                          + R8[b0+64] + R8[b0+65] + R8[b0+72] + R8[b0+73]);
    }
    __syncthreads();
    if (tid < 8) {
        int w = tid & 1, h = (tid >> 1) & 1, d = tid >> 2;
        int b0 = ((2 * d) * 4 + 2 * h) * 4 + 2 * w;
        R2[tid] = 0.125f * (R4[b0] + R4[b0+1] + R4[b0+4] + R4[b0+5]
                          + R4[b0+16] + R4[b0+17] + R4[b0+20] + R4[b0+21]);
    }
    __syncthreads();
    if (tid == 0) {
        float r1 = 0.125f * (R2[0]+R2[1]+R2[2]+R2[3]+R2[4]+R2[5]+R2[6]+R2[7]);
        W1a[0] = r1 / (-6.f);
        if (o_r) o_r[0] = r1;
    }
    __syncthreads();
    if (tid < 8) {
        int w = tid & 1, h = (tid >> 1) & 1, d = tid >> 2;
        W2[tid] = mgcell(W1a, 1, R2[tid], d, h, w, 2);
    }
    __syncthreads();
    if (tid < 64) {
        int w = tid & 3, h = (tid >> 2) & 3, d = tid >> 4;
        W4[tid] = mgcell(W2, 2, R4[tid], d, h, w, 4);
    }
    __syncthreads();
    {
        int w = tid & 7, h = (tid >> 3) & 7, d = tid >> 6;
        W8[tid] = mgcell(W4, 4, R8[tid], d, h, w, 8);
    }
    __syncthreads();
    #pragma unroll
    for (int k = tid; k < 4096; k += 512) {
        int w = k & 15, h = (k >> 4) & 15, d = k >> 8;
        W16g[k] = mgcell(W8, 8, R16[k], d, h, w, 16);
    }
}

// m=32 MG level, grid-wide (W16 tiny and cache-hot)
__global__ void __launch_bounds__(256) k_mg32(
    const float* __restrict__ W16, const float* __restrict__ Rp2, float* __restrict__ W32)
{
    const int t = blockIdx.x * 256 + threadIdx.x;   // 32768
    const int w = t & 31, h = (t >> 5) & 31, d = t >> 10;
    W32[t] = mgcell(W16, 16, Rp2[t], d, h, w, 32);
}

// ---------------------------------------------------------------------------
// p-update with m=64 MG level fused (reads W32 from global; L2-hot)
// ---------------------------------------------------------------------------
__global__ void __launch_bounds__(256) k_pupdate(
    const float* __restrict__ pold, const float* __restrict__ W32,
    const float* __restrict__ Rp1, const float* __restrict__ r0,
    float* __restrict__ pnew, float* __restrict__ wmg_out)
{
    const int w4 = threadIdx.x << 2;
    const int h  = (blockIdx.y << 3) + threadIdx.y;
    const int d  = blockIdx.z;
    const int cb = ix(d, h, w4);

    const int d64 = d >> 1, h64 = h >> 1, cw0 = w4 >> 1;
    const int crow = (d64 * 64 + h64) * 64 + cw0;
    const float r64_0 = Rp1[crow], r64_1 = Rp1[crow + 1];
    const float4 r4 = ld4(r0, cb);
    const float4 po = ld4(pold, cb);

    const float mg0 = mgcell(W32, 32, r64_0, d64, h64, cw0,     64);
    const float mg1 = mgcell(W32, 32, r64_1, d64, h64, cw0 + 1, 64);
    const float4 wv = make_float4(mg0, mg0, mg1, mg1);
    const float4 pn = po - wv - make_float4(r4.x/(-6.f), r4.y/(-6.f), r4.z/(-6.f), r4.w/(-6.f));
    st4(pnew, cb, pn);
    if (wmg_out) st4(wmg_out, cb, wv);
}

// ---------------------------------------------------------------------------
__global__ void __launch_bounds__(256) k_final(
    const float* __restrict__ U1, const float* __restrict__ V1, const float* __restrict__ W1,
    const float* __restrict__ Pf, const float* __restrict__ SG, const float* __restrict__ DT,
    float* __restrict__ OU, float* __restrict__ OV, float* __restrict__ OW)
{
    const int w4 = threadIdx.x << 2;
    const int h  = (blockIdx.y << 3) + threadIdx.y;
    const int hS = cl(h - 1), hN = cl(h + 1);
    IDX6(blockIdx.z);

    S7 p = ld7(Pf, cb, nb, sb, bb, tb, w4);
    const float4 sg = ld4(SG, cb);
    const float4 u1 = ld4(U1, cb), v1 = ld4(V1, cb), w1 = ld4(W1, cb);
    const float dt = DT[0];

    const float4 fc = rcp4(dt, sg);
    float4 gpx = 0.5f * (eastv(p) - westv(p));
    float4 gpy = 0.5f * (p.n - p.s);
    float4 gpz = 0.5f * (p.t - p.b);
    st4(OU, cb, (u1 - dt * gpx) * fc);
    st4(OV, cb, (v1 - dt * gpy) * fc);
    st4(OW, cb, (w1 - dt * gpz) * fc);
}

// ---------------------------------------------------------------------------
extern "C" void kernel_launch(void* const* d_in, const int* in_sizes, int n_in,
                              void* d_out, int out_size)
{
    const float* U  = (const float*)d_in[0];
    const float* V  = (const float*)d_in[1];
    const float* W_ = (const float*)d_in[2];
    const float* P  = (const float*)d_in[3];
    const float* SG = (const float*)d_in[4];
    const float* DT = (const float*)d_in[5];

    float* out   = (float*)d_out;
    float* o_u   = out;
    float* o_v   = out + (size_t)N3;
    float* o_w   = out + 2 * (size_t)N3;
    float* o_p   = out + 3 * (size_t)N3;
    float* o_wmg = out + 4 * (size_t)N3;
    float* o_r   = out + 5 * (size_t)N3;

    float* S = nullptr;
    cudaGetSymbolAddress((void**)&S, g_scratch);
    float* BU = S;
    float* BV = S + (size_t)N3;
    float* BW = S + 2 * (size_t)N3;
    float* U1 = S + 3 * (size_t)N3;
    float* V1 = S + 4 * (size_t)N3;
    float* W1 = S + 5 * (size_t)N3;
    float* B  = S + 6 * (size_t)N3;
    float* R0 = S + 7 * (size_t)N3;
    float* P1 = S + 8 * (size_t)N3;
    float* Rp1 = S + 9 * (size_t)N3;     // 64^3
    float* Rp2 = Rp1 + 262144;           // 32^3
    float* W32 = Rp2 + 32768;            // 32^3
    float* W16 = W32 + 32768;            // 16^3

    dim3 blkF(32, 4), grdF(1, 32, 128);     // fat kernels, 128 thr
    dim3 blkR(32, 8), grdR(1, 16, 32);      // residual (4 planes/block)
    dim3 grdP(1, 16, 128);                  // full-depth grids with blkR

    k_predictor<<<grdF, blkF>>>(U, V, W_, P, SG, DT, BU, BV, BW);
    k_corrector<<<grdF, blkF>>>(BU, BV, BW, U, V, W_, P, SG, DT, U1, V1, W1);

    // iteration 0 (div + restrictions fused into residual)
    k_residdiv<<<grdR, blkR>>>(P, U1, V1, W1, DT, B, R0, Rp1, Rp2);
    k_coarse16<<<1, 512>>>(Rp2, W16, nullptr);
    k_mg32<<<128, 256>>>(W16, Rp2, W32);
    k_pupdate<<<grdP, blkR>>>(P, W32, Rp1, R0, P1, nullptr);

    // iteration 1
    k_resid<<<grdR, blkR>>>(P1, B, R0, Rp1, Rp2);
    k_coarse16<<<1, 512>>>(Rp2, W16, o_r);
    k_mg32<<<128, 256>>>(W16, Rp2, W32);
    k_pupdate<<<grdP, blkR>>>(P1, W32, Rp1, R0, o_p, o_wmg);

    k_final<<<grdP, blkR>>>(U1, V1, W1, o_p, SG, DT, o_u, o_v, o_w);
}

// round 11
// speedup vs baseline: 1.0722x; 1.0446x over previous
#include <cuda_runtime.h>

#define N   128
#define N3  (N*N*N)

// BU BV BW U1 V1 W1 B P1 (8 x N3) + Rp1(64^3) + Rp2(32^3) + W32(32^3) + W16(16^3)
__device__ float g_scratch[8 * (size_t)N3 + 262144 + 2 * 32768 + 4096];

static __device__ __forceinline__ int cl(int x) { return x < 0 ? 0 : (x > N - 1 ? N - 1 : x); }
static __device__ __forceinline__ int ix(int d, int h, int w) { return (d << 14) + (h << 7) + w; }

static __device__ __forceinline__ float4 ld4(const float* __restrict__ p, int i) {
    return *reinterpret_cast<const float4*>(p + i);
}
static __device__ __forceinline__ void st4(float* __restrict__ p, int i, float4 v) {
    *reinterpret_cast<float4*>(p + i) = v;
}
static __device__ __forceinline__ float4 operator+(float4 a, float4 b) { return make_float4(a.x+b.x, a.y+b.y, a.z+b.z, a.w+b.w); }
static __device__ __forceinline__ float4 operator-(float4 a, float4 b) { return make_float4(a.x-b.x, a.y-b.y, a.z-b.z, a.w-b.w); }
static __device__ __forceinline__ float4 operator*(float s, float4 a) { return make_float4(s*a.x, s*a.y, s*a.z, s*a.w); }
static __device__ __forceinline__ float4 operator*(float4 a, float4 b) { return make_float4(a.x*b.x, a.y*b.y, a.z*b.z, a.w*b.w); }

struct S7 { float4 c, n, s, b, t; float wl, wr; };

static __device__ __forceinline__ S7 ld7(const float* __restrict__ A,
                                         int cb, int nb, int sb, int bb, int tb, int w4) {
    S7 r;
    r.c = ld4(A, cb); r.n = ld4(A, nb); r.s = ld4(A, sb); r.b = ld4(A, bb); r.t = ld4(A, tb);
    r.wl = (w4 > 0)   ? A[cb - 1] : r.c.x;
    r.wr = (w4 < 124) ? A[cb + 4] : r.c.w;
    return r;
}
static __device__ __forceinline__ float4 westv(const S7& s) { return make_float4(s.wl, s.c.x, s.c.y, s.c.z); }
static __device__ __forceinline__ float4 eastv(const S7& s) { return make_float4(s.c.y, s.c.z, s.c.w, s.wr); }

static __device__ __forceinline__ float4 rcp4(float dt, float4 g) {
    return make_float4(1.f/(1.f+dt*g.x), 1.f/(1.f+dt*g.y), 1.f/(1.f+dt*g.z), 1.f/(1.f+dt*g.w));
}
static __device__ __forceinline__ void scale7(S7& u, const S7& f) {
    u.c = u.c * f.c; u.n = u.n * f.n; u.s = u.s * f.s; u.b = u.b * f.b; u.t = u.t * f.t;
    u.wl *= f.wl; u.wr *= f.wr;
}

#define IDX6(dd)                                      \
    const int d = (dd);                               \
    const int dB = cl(d - 1), dT = cl(d + 1);         \
    const int cb = ix(d, h, w4);                      \
    const int nb = ix(d, hN, w4), sb = ix(d, hS, w4); \
    const int bb = ix(dB, h, w4), tb = ix(dT, h, w4);

// ---------------------------------------------------------------------------
__global__ void __launch_bounds__(128) k_predictor(
    const float* __restrict__ U, const float* __restrict__ V, const float* __restrict__ W_,
    const float* __restrict__ P, const float* __restrict__ SG, const float* __restrict__ DT,
    float* __restrict__ BU, float* __restrict__ BV, float* __restrict__ BW)
{
    const int w4 = threadIdx.x << 2;
    const int h  = (blockIdx.y << 2) + threadIdx.y;
    const int hS = cl(h - 1), hN = cl(h + 1);
    IDX6(blockIdx.z);

    S7 g  = ld7(SG, cb, nb, sb, bb, tb, w4);
    S7 p  = ld7(P,  cb, nb, sb, bb, tb, w4);
    S7 su = ld7(U,  cb, nb, sb, bb, tb, w4);
    S7 sv = ld7(V,  cb, nb, sb, bb, tb, w4);
    S7 sw = ld7(W_, cb, nb, sb, bb, tb, w4);
    const float dt = DT[0];

    S7 f;
    f.c = rcp4(dt, g.c); f.n = rcp4(dt, g.n); f.s = rcp4(dt, g.s);
    f.b = rcp4(dt, g.b); f.t = rcp4(dt, g.t);
    f.wl = 1.f/(1.f+dt*g.wl); f.wr = 1.f/(1.f+dt*g.wr);

    scale7(su, f); scale7(sv, f); scale7(sw, f);
    const float4 uc = su.c, vc = sv.c, wc = sw.c;

    float4 gpx = 0.5f * (eastv(p) - westv(p));
    float4 gpy = 0.5f * (p.n - p.s);
    float4 gpz = 0.5f * (p.t - p.b);

    {
        float4 west = westv(su); if (w4 == 0) west.x = 1.0f;
        float4 east = eastv(su);
        float4 lap = west + east + su.n + su.s + su.b + su.t - 6.f * su.c;
        float4 ax = 0.5f * (east - west), ay = 0.5f * (su.n - su.s), az = 0.5f * (su.t - su.b);
        st4(BU, cb, (uc + 0.5f*dt*(lap - uc*ax - vc*ay - wc*az) - dt*gpx) * f.c);
    }
    {
        float4 west = westv(sv), east = eastv(sv);
        float4 lap = west + east + sv.n + sv.s + sv.b + sv.t - 6.f * sv.c;
        float4 ax = 0.5f * (east - west), ay = 0.5f * (sv.n - sv.s), az = 0.5f * (sv.t - sv.b);
        st4(BV, cb, (vc + 0.5f*dt*(lap - uc*ax - vc*ay - wc*az) - dt*gpy) * f.c);
    }
    {
        float4 west = westv(sw), east = eastv(sw);
        float4 lap = west + east + sw.n + sw.s + sw.b + sw.t - 6.f * sw.c;
        float4 ax = 0.5f * (east - west), ay = 0.5f * (sw.n - sw.s), az = 0.5f * (sw.t - sw.b);
        st4(BW, cb, (wc + 0.5f*dt*(lap - uc*ax - vc*ay - wc*az) - dt*gpz) * f.c);
    }
}

// ---------------------------------------------------------------------------
__global__ void __launch_bounds__(128) k_corrector(
    const float* __restrict__ BU, const float* __restrict__ BV, const float* __restrict__ BW,
    const float* __restrict__ U, const float* __restrict__ V, const float* __restrict__ W_,
    const float* __restrict__ P, const float* __restrict__ SG, const float* __restrict__ DT,
    float* __restrict__ U1, float* __restrict__ V1, float* __restrict__ W1)
{
    const int w4 = threadIdx.x << 2;
    const int h  = (blockIdx.y << 2) + threadIdx.y;
    const int hS = cl(h - 1), hN = cl(h + 1);
    IDX6(blockIdx.z);

    const float4 sg = ld4(SG, cb);
    const float4 Uc = ld4(U, cb), Vc = ld4(V, cb), Wc = ld4(W_, cb);
    S7 p = ld7(P,  cb, nb, sb, bb, tb, w4);
    S7 a = ld7(BU, cb, nb, sb, bb, tb, w4);
    S7 b = ld7(BV, cb, nb, sb, bb, tb, w4);
    S7 c = ld7(BW, cb, nb, sb, bb, tb, w4);
    const float dt = DT[0];

    const float4 fc = rcp4(dt, sg);
    const float4 uc = Uc * fc, vc = Vc * fc, wc = Wc * fc;
    const float4 buc = a.c, bvc = b.c, bwc = c.c;

    float4 gpx = 0.5f * (eastv(p) - westv(p));
    float4 gpy = 0.5f * (p.n - p.s);
    float4 gpz = 0.5f * (p.t - p.b);

    {
        float4 west = westv(a); if (w4 == 0) west.x = 1.0f;
        float4 east = eastv(a);
        float4 lap = west + east + a.n + a.s + a.b + a.t - 6.f * a.c;
        float4 ax = 0.5f * (east - west), ay = 0.5f * (a.n - a.s), az = 0.5f * (a.t - a.b);
        st4(U1, cb, (uc + dt*(lap - buc*ax - bvc*ay - bwc*az) - dt*gpx) * fc);
    }
    {
        float4 west = westv(b), east = eastv(b);
        float4 lap = west + east + b.n + b.s + b.b + b.t - 6.f * b.c;
        float4 ax = 0.5f * (east - west), ay = 0.5f * (b.n - b.s), az = 0.5f * (b.t - b.b);
        st4(V1, cb, (vc + dt*(lap - buc*ax - bvc*ay - bwc*az) - dt*gpy) * fc);
    }
    {
        float4 west = westv(c), east = eastv(c);
        float4 lap = west + east + c.n + c.s + c.b + c.t - 6.f * c.c;
        float4 ax = 0.5f * (east - west), ay = 0.5f * (c.n - c.s), az = 0.5f * (c.t - c.b);
        st4(W1, cb, (wc + dt*(lap - buc*ax - bvc*ay - bwc*az) - dt*gpz) * fc);
    }
}

// ---------------------------------------------------------------------------
// Iter-0 fused: div + residual + Ppre(=p - r0/diag) + 128->64 + 64->32 restrictions.
// Block covers 4 d-planes (2 pair-passes), h:8, w:128. Grid (1,16,32).
// ---------------------------------------------------------------------------
__global__ void __launch_bounds__(256) k_residdiv(
    const float* __restrict__ P, const float* __restrict__ U1,
    const float* __restrict__ V1, const float* __restrict__ W1,
    const float* __restrict__ DT,
    float* __restrict__ B, float* __restrict__ PP,
    float* __restrict__ Rp1, float* __restrict__ Rp2)
{
    __shared__ float sred[8][64];
    __shared__ float c64buf[2][4][64];
    const int w4 = threadIdx.x << 2;
    const int h  = (blockIdx.y << 3) + threadIdx.y;
    const int hS = cl(h - 1), hN = cl(h + 1);
    const int tid = threadIdx.y * 32 + threadIdx.x;
    const float dt = DT[0];
    const float rdt = -1.f / dt;

    #pragma unroll
    for (int pair = 0; pair < 2; ++pair) {
        S7 pp[2]; float4 u1c[2], vn[2], vs[2], wb[2], wt[2];
        float uwl[2], uwr[2]; int cbs[2];
        #pragma unroll
        for (int d2 = 0; d2 < 2; ++d2) {
            IDX6((blockIdx.z << 2) + (pair << 1) + d2);
            cbs[d2] = cb;
            pp[d2]  = ld7(P, cb, nb, sb, bb, tb, w4);
            u1c[d2] = ld4(U1, cb);
            uwl[d2] = (w4 > 0)   ? U1[cb - 1] : u1c[d2].x;
            uwr[d2] = (w4 < 124) ? U1[cb + 4] : u1c[d2].w;
            vn[d2] = ld4(V1, nb); vs[d2] = ld4(V1, sb);
            wt[d2] = ld4(W1, tb); wb[d2] = ld4(W1, bb);
        }
        float acc0 = 0.f, acc1 = 0.f;
        #pragma unroll
        for (int d2 = 0; d2 < 2; ++d2) {
            float wl = uwl[d2]; if (w4 == 0) wl = 1.0f;
            float4 west = make_float4(wl, u1c[d2].x, u1c[d2].y, u1c[d2].z);
            float4 east = make_float4(u1c[d2].y, u1c[d2].z, u1c[d2].w, uwr[d2]);
            float4 b4 = rdt * (0.5f*(east - west) + 0.5f*(vn[d2] - vs[d2]) + 0.5f*(wt[d2] - wb[d2]));
            st4(B, cbs[d2], b4);

            float4 pw = westv(pp[d2]), pe = eastv(pp[d2]);
            float4 lap = pw + pe + pp[d2].n + pp[d2].s + pp[d2].b + pp[d2].t - 6.f * pp[d2].c;
            float4 rr = lap - b4;
            st4(PP, cbs[d2], pp[d2].c - make_float4(rr.x/(-6.f), rr.y/(-6.f), rr.z/(-6.f), rr.w/(-6.f)));
            acc0 += rr.x + rr.y;
            acc1 += rr.z + rr.w;
        }
        sred[threadIdx.y][threadIdx.x * 2]     = acc0;
        sred[threadIdx.y][threadIdx.x * 2 + 1] = acc1;
        __syncthreads();
        {
            int cw = tid & 63, chh = tid >> 6;
            float v = 0.125f * (sred[2 * chh][cw] + sred[2 * chh + 1][cw]);
            int dc = (blockIdx.z << 1) + pair, hc = (blockIdx.y << 2) + chh;
            Rp1[(dc * 64 + hc) * 64 + cw] = v;
            c64buf[pair][chh][cw] = v;
        }
        __syncthreads();
    }
    if (tid < 64) {
        int wc2 = tid & 31, hc2 = tid >> 5;
        float s = 0.f;
        #pragma unroll
        for (int dc = 0; dc < 2; ++dc)
            #pragma unroll
            for (int hh = 0; hh < 2; ++hh)
                s += c64buf[dc][hc2 * 2 + hh][wc2 * 2] + c64buf[dc][hc2 * 2 + hh][wc2 * 2 + 1];
        Rp2[((blockIdx.z) * 32 + (blockIdx.y << 1) + hc2) * 32 + wc2] = 0.125f * s;
    }
}

// ---------------------------------------------------------------------------
// Iter-1 residual: Ppre = p - (lap(p)-B)/diag, + restrictions.
// ---------------------------------------------------------------------------
__global__ void __launch_bounds__(256) k_resid(
    const float* __restrict__ P, const float* __restrict__ B,
    float* __restrict__ PP, float* __restrict__ Rp1, float* __restrict__ Rp2)
{
    __shared__ float sred[8][64];
    __shared__ float c64buf[2][4][64];
    const int w4 = threadIdx.x << 2;
    const int h  = (blockIdx.y << 3) + threadIdx.y;
    const int hS = cl(h - 1), hN = cl(h + 1);
    const int tid = threadIdx.y * 32 + threadIdx.x;

    #pragma unroll
    for (int pair = 0; pair < 2; ++pair) {
        S7 pp[2]; float4 bc[2]; int cbs[2];
        #pragma unroll
        for (int d2 = 0; d2 < 2; ++d2) {
            IDX6((blockIdx.z << 2) + (pair << 1) + d2);
            cbs[d2] = cb;
            pp[d2] = ld7(P, cb, nb, sb, bb, tb, w4);
            bc[d2] = ld4(B, cb);
        }
        float acc0 = 0.f, acc1 = 0.f;
        #pragma unroll
        for (int d2 = 0; d2 < 2; ++d2) {
            float4 pw = westv(pp[d2]), pe = eastv(pp[d2]);
            float4 lap = pw + pe + pp[d2].n + pp[d2].s + pp[d2].b + pp[d2].t - 6.f * pp[d2].c;
            float4 rr = lap - bc[d2];
            st4(PP, cbs[d2], pp[d2].c - make_float4(rr.x/(-6.f), rr.y/(-6.f), rr.z/(-6.f), rr.w/(-6.f)));
            acc0 += rr.x + rr.y;
            acc1 += rr.z + rr.w;
        }
        sred[threadIdx.y][threadIdx.x * 2]     = acc0;
        sred[threadIdx.y][threadIdx.x * 2 + 1] = acc1;
        __syncthreads();
        {
            int cw = tid & 63, chh = tid >> 6;
            float v = 0.125f * (sred[2 * chh][cw] + sred[2 * chh + 1][cw]);
            int dc = (blockIdx.z << 1) + pair, hc = (blockIdx.y << 2) + chh;
            Rp1[(dc * 64 + hc) * 64 + cw] = v;
            c64buf[pair][chh][cw] = v;
        }
        __syncthreads();
    }
    if (tid < 64) {
        int wc2 = tid & 31, hc2 = tid >> 5;
        float s = 0.f;
        #pragma unroll
        for (int dc = 0; dc < 2; ++dc)
            #pragma unroll
            for (int hh = 0; hh < 2; ++hh)
                s += c64buf[dc][hc2 * 2 + hh][wc2 * 2] + c64buf[dc][hc2 * 2 + hh][wc2 * 2 + 1];
        Rp2[((blockIdx.z) * 32 + (blockIdx.y << 1) + hc2) * 32 + wc2] = 0.125f * s;
    }
}

static __device__ __forceinline__ float mgcell(const float* __restrict__ Wp, int mc,
                                               float r, int d, int h, int w, int m)
{
    auto g = [&](int dd, int hh, int ww) -> float {
        if (dd < 0 || dd >= m || hh < 0 || hh >= m || ww < 0 || ww >= m) return 0.f;
        return Wp[((dd >> 1) * mc + (hh >> 1)) * mc + (ww >> 1)];
    };
    float wc = g(d, h, w);
    float lap = g(d-1,h,w) + g(d+1,h,w) + g(d,h-1,w) + g(d,h+1,w) + g(d,h,w-1) + g(d,h,w+1) - 6.f * wc;
    return wc - lap / (-6.f) + r / (-6.f);
}

// padded-coarse read: fine index ff in [-1, m] maps to ((ff>>1)+1) in [0, mc+1]
static __device__ __forceinline__ float gpad(const float* __restrict__ W, int p1, int p2,
                                             int dd, int hh, int ww)
{
    return W[((dd >> 1) + 1) * p1 + ((hh >> 1) + 1) * p2 + ((ww >> 1) + 1)];
}
static __device__ __forceinline__ float mgpad(const float* __restrict__ W, int p1, int p2,
                                              float r, int d, int h, int w)
{
    float wc = gpad(W, p1, p2, d, h, w);
    float lap = gpad(W, p1, p2, d-1, h, w) + gpad(W, p1, p2, d+1, h, w)
              + gpad(W, p1, p2, d, h-1, w) + gpad(W, p1, p2, d, h+1, w)
              + gpad(W, p1, p2, d, h, w-1) + gpad(W, p1, p2, d, h, w+1) - 6.f * wc;
    return wc - lap / (-6.f) + r / (-6.f);
}

// ---------------------------------------------------------------------------
// Single-block coarse solver (1024 thr): 32^3 -> 16^3 restriction, pyramid
// down to 1, solve back up to W16. Zero-padded smem => branch-free mgcells.
// ---------------------------------------------------------------------------
__global__ void __launch_bounds__(1024) k_coarse16(
    const float* __restrict__ Rp2g, float* __restrict__ W16g, float* __restrict__ o_r)
{
    __shared__ float R16[4096], R8[512], R4[64], R2[8];
    __shared__ float W8p[1000], W4p[216], W2p[64], W1p[27];
    const int tid = threadIdx.x;

    if (tid < 1000) W8p[tid] = 0.f;
    else if (tid < 1000 + 24) { /* idle lanes */ }
    if (tid >= 0 && tid < 216) W4p[tid] = 0.f;
    if (tid >= 256 && tid < 320) W2p[tid - 256] = 0.f;
    if (tid >= 512 && tid < 539) W1p[tid - 512] = 0.f;

    // 32 -> 16: 4 cells per thread, 8 x float4 global reads
    {
        const int w0 = (tid & 3) << 2;
        const int r = tid >> 2;          // 0..255
        const int d16 = r >> 4, h16 = r & 15;
        const int fb = ((2 * d16) * 32 + 2 * h16) * 32 + 2 * w0;
        float a[8], b[8], c[8], e[8];
        *reinterpret_cast<float4*>(a)     = ld4(Rp2g, fb);
        *reinterpret_cast<float4*>(a + 4) = ld4(Rp2g, fb + 4);
        *reinterpret_cast<float4*>(b)     = ld4(Rp2g, fb + 32);
        *reinterpret_cast<float4*>(b + 4) = ld4(Rp2g, fb + 36);
        *reinterpret_cast<float4*>(c)     = ld4(Rp2g, fb + 1024);
        *reinterpret_cast<float4*>(c + 4) = ld4(Rp2g, fb + 1028);
        *reinterpret_cast<float4*>(e)     = ld4(Rp2g, fb + 1056);
        *reinterpret_cast<float4*>(e + 4) = ld4(Rp2g, fb + 1060);
        #pragma unroll
        for (int k = 0; k < 4; ++k)
            R16[(d16 * 16 + h16) * 16 + w0 + k] =
                0.125f * (a[2*k] + a[2*k+1] + b[2*k] + b[2*k+1]
                        + c[2*k] + c[2*k+1] + e[2*k] + e[2*k+1]);
    }
    __syncthreads();
    if (tid < 512) {   // 16 -> 8
        int w = tid & 7, h = (tid >> 3) & 7, d = tid >> 6;
        int b0 = ((2 * d) * 16 + 2 * h) * 16 + 2 * w;
        R8[tid] = 0.125f * (R16[b0] + R16[b0+1] + R16[b0+16] + R16[b0+17]
                          + R16[b0+256] + R16[b0+257] + R16[b0+272] + R16[b0+273]);
    }
    __syncthreads();
    if (tid < 64) {    // 8 -> 4
        int w = tid & 3, h = (tid >> 2) & 3, d = tid >> 4;
        int b0 = ((2 * d) * 8 + 2 * h) * 8 + 2 * w;
        R4[tid] = 0.125f * (R8[b0] + R8[b0+1] + R8[b0+8] + R8[b0+9]
                          + R8[b0+64] + R8[b0+65] + R8[b0+72] + R8[b0+73]);
    }
    __syncthreads();
    if (tid < 8) {     // 4 -> 2
        int w = tid & 1, h = (tid >> 1) & 1, d = tid >> 2;
        int b0 = ((2 * d) * 4 + 2 * h) * 4 + 2 * w;
        R2[tid] = 0.125f * (R4[b0] + R4[b0+1] + R4[b0+4] + R4[b0+5]
                          + R4[b0+16] + R4[b0+17] + R4[b0+20] + R4[b0+21]);
    }
    __syncthreads();
    if (tid == 0) {    // 2 -> 1 + coarsest solve; W1p center = (1,1,1)
        float r1 = 0.125f * (R2[0]+R2[1]+R2[2]+R2[3]+R2[4]+R2[5]+R2[6]+R2[7]);
        W1p[13] = r1 / (-6.f);
        if (o_r) o_r[0] = r1;
    }
    __syncthreads();
    if (tid < 8) {     // m = 2 -> W2p (4^3, pitches 16,4)
        int w = tid & 1, h = (tid >> 1) & 1, d = tid >> 2;
        W2p[(d+1)*16 + (h+1)*4 + (w+1)] = mgpad(W1p, 9, 3, R2[tid], d, h, w);
    }
    __syncthreads();
    if (tid < 64) {    // m = 4 -> W4p (6^3, pitches 36,6)
        int w = tid & 3, h = (tid >> 2) & 3, d = tid >> 4;
        W4p[(d+1)*36 + (h+1)*6 + (w+1)] = mgpad(W2p, 16, 4, R4[tid], d, h, w);
    }
    __syncthreads();
    if (tid < 512) {   // m = 8 -> W8p (10^3, pitches 100,10)
        int w = tid & 7, h = (tid >> 3) & 7, d = tid >> 6;
        W8p[(d+1)*100 + (h+1)*10 + (w+1)] = mgpad(W4p, 36, 6, R8[tid], d, h, w);
    }
    __syncthreads();
    #pragma unroll
    for (int k = tid; k < 4096; k += 1024) {   // m = 16 -> global
        int w = k & 15, h = (k >> 4) & 15, d = k >> 8;
        W16g[k] = mgpad(W8p, 100, 10, R16[k], d, h, w);
    }
}

// m=32 MG level, grid-wide (W16 tiny and cache-hot)
__global__ void __launch_bounds__(256) k_mg32(
    const float* __restrict__ W16, const float* __restrict__ Rp2, float* __restrict__ W32)
{
    const int t = blockIdx.x * 256 + threadIdx.x;   // 32768
    const int w = t & 31, h = (t >> 5) & 31, d = t >> 10;
    W32[t] = mgcell(W16, 16, Rp2[t], d, h, w, 32);
}

// ---------------------------------------------------------------------------
// In-place p-update with m=64 MG level fused: Pio -= mg64(W32, Rp1)
// ---------------------------------------------------------------------------
__global__ void __launch_bounds__(256) k_pupdate(
    float* __restrict__ Pio, const float* __restrict__ W32,
    const float* __restrict__ Rp1, float* __restrict__ wmg_out)
{
    const int w4 = threadIdx.x << 2;
    const int h  = (blockIdx.y << 3) + threadIdx.y;
    const int d  = blockIdx.z;
    const int cb = ix(d, h, w4);

    const int d64 = d >> 1, h64 = h >> 1, cw0 = w4 >> 1;
    const int crow = (d64 * 64 + h64) * 64 + cw0;
    const float r64_0 = Rp1[crow], r64_1 = Rp1[crow + 1];
    const float4 po = ld4(Pio, cb);

    const float mg0 = mgcell(W32, 32, r64_0, d64, h64, cw0,     64);
    const float mg1 = mgcell(W32, 32, r64_1, d64, h64, cw0 + 1, 64);
    const float4 wv = make_float4(mg0, mg0, mg1, mg1);
    st4(Pio, cb, po - wv);
    if (wmg_out) st4(wmg_out, cb, wv);
}

// ---------------------------------------------------------------------------
__global__ void __launch_bounds__(256) k_final(
    const float* __restrict__ U1, const float* __restrict__ V1, const float* __restrict__ W1,
    const float* __restrict__ Pf, const float* __restrict__ SG, const float* __restrict__ DT,
    float* __restrict__ OU, float* __restrict__ OV, float* __restrict__ OW)
{
    const int w4 = threadIdx.x << 2;
    const int h  = (blockIdx.y << 3) + threadIdx.y;
    const int hS = cl(h - 1), hN = cl(h + 1);
    IDX6(blockIdx.z);

    S7 p = ld7(Pf, cb, nb, sb, bb, tb, w4);
    const float4 sg = ld4(SG, cb);
    const float4 u1 = ld4(U1, cb), v1 = ld4(V1, cb), w1 = ld4(W1, cb);
    const float dt = DT[0];

    const float4 fc = rcp4(dt, sg);
    float4 gpx = 0.5f * (eastv(p) - westv(p));
    float4 gpy = 0.5f * (p.n - p.s);
    float4 gpz = 0.5f * (p.t - p.b);
    st4(OU, cb, (u1 - dt * gpx) * fc);
    st4(OV, cb, (v1 - dt * gpy) * fc);
    st4(OW, cb, (w1 - dt * gpz) * fc);
}

// ---------------------------------------------------------------------------
extern "C" void kernel_launch(void* const* d_in, const int* in_sizes, int n_in,
                              void* d_out, int out_size)
{
    const float* U  = (const float*)d_in[0];
    const float* V  = (const float*)d_in[1];
    const float* W_ = (const float*)d_in[2];
    const float* P  = (const float*)d_in[3];
    const float* SG = (const float*)d_in[4];
    const float* DT = (const float*)d_in[5];

    float* out   = (float*)d_out;
    float* o_u   = out;
    float* o_v   = out + (size_t)N3;
    float* o_w   = out + 2 * (size_t)N3;
    float* o_p   = out + 3 * (size_t)N3;
    float* o_wmg = out + 4 * (size_t)N3;
    float* o_r   = out + 5 * (size_t)N3;

    float* S = nullptr;
    cudaGetSymbolAddress((void**)&S, g_scratch);
    float* BU = S;
    float* BV = S + (size_t)N3;
    float* BW = S + 2 * (size_t)N3;
    float* U1 = S + 3 * (size_t)N3;
    float* V1 = S + 4 * (size_t)N3;
    float* W1 = S + 5 * (size_t)N3;
    float* B  = S + 6 * (size_t)N3;
    float* P1 = S + 7 * (size_t)N3;
    float* Rp1 = S + 8 * (size_t)N3;     // 64^3
    float* Rp2 = Rp1 + 262144;           // 32^3
    float* W32 = Rp2 + 32768;            // 32^3
    float* W16 = W32 + 32768;            // 16^3

    dim3 blkF(32, 4), grdF(1, 32, 128);     // fat kernels, 128 thr
    dim3 blkR(32, 8), grdR(1, 16, 32);      // residual (4 planes/block)
    dim3 grdP(1, 16, 128);                  // full-depth grids with blkR

    k_predictor<<<grdF, blkF>>>(U, V, W_, P, SG, DT, BU, BV, BW);
    k_corrector<<<grdF, blkF>>>(BU, BV, BW, U, V, W_, P, SG, DT, U1, V1, W1);

    // iteration 0: Ppre -> P1, then P1 -= wmg (in place)
    k_residdiv<<<grdR, blkR>>>(P, U1, V1, W1, DT, B, P1, Rp1, Rp2);
    k_coarse16<<<1, 1024>>>(Rp2, W16, nullptr);
    k_mg32<<<128, 256>>>(W16, Rp2, W32);
    k_pupdate<<<grdP, blkR>>>(P1, W32, Rp1, nullptr);

    // iteration 1: Ppre -> o_p, then o_p -= wmg (in place) + o_wmg
    k_resid<<<grdR, blkR>>>(P1, B, o_p, Rp1, Rp2);
    k_coarse16<<<1, 1024>>>(Rp2, W16, o_r);
    k_mg32<<<128, 256>>>(W16, Rp2, W32);
    k_pupdate<<<grdP, blkR>>>(o_p, W32, Rp1, o_wmg);

    k_final<<<grdP, blkR>>>(U1, V1, W1, o_p, SG, DT, o_u, o_v, o_w);
}

// round 12
// speedup vs baseline: 1.0737x; 1.0014x over previous
#include <cuda_runtime.h>

#define N   128
#define N3  (N*N*N)

// BU BV BW U1 V1 W1 B P1 (8 x N3) + Rp1(64^3) + Rp2(32^3) + W32(32^3) + W16(16^3) + Rp3(2x16^3)
__device__ float g_scratch[8 * (size_t)N3 + 262144 + 2 * 32768 + 4096 + 8192];

static __device__ __forceinline__ int cl(int x) { return x < 0 ? 0 : (x > N - 1 ? N - 1 : x); }
static __device__ __forceinline__ int ix(int d, int h, int w) { return (d << 14) + (h << 7) + w; }

static __device__ __forceinline__ float4 ld4(const float* __restrict__ p, int i) {
    return *reinterpret_cast<const float4*>(p + i);
}
static __device__ __forceinline__ void st4(float* __restrict__ p, int i, float4 v) {
    *reinterpret_cast<float4*>(p + i) = v;
}
static __device__ __forceinline__ float4 operator+(float4 a, float4 b) { return make_float4(a.x+b.x, a.y+b.y, a.z+b.z, a.w+b.w); }
static __device__ __forceinline__ float4 operator-(float4 a, float4 b) { return make_float4(a.x-b.x, a.y-b.y, a.z-b.z, a.w-b.w); }
static __device__ __forceinline__ float4 operator*(float s, float4 a) { return make_float4(s*a.x, s*a.y, s*a.z, s*a.w); }
static __device__ __forceinline__ float4 operator*(float4 a, float4 b) { return make_float4(a.x*b.x, a.y*b.y, a.z*b.z, a.w*b.w); }

struct S7 { float4 c, n, s, b, t; float wl, wr; };

static __device__ __forceinline__ S7 ld7(const float* __restrict__ A,
                                         int cb, int nb, int sb, int bb, int tb, int w4) {
    S7 r;
    r.c = ld4(A, cb); r.n = ld4(A, nb); r.s = ld4(A, sb); r.b = ld4(A, bb); r.t = ld4(A, tb);
    r.wl = (w4 > 0)   ? A[cb - 1] : r.c.x;
    r.wr = (w4 < 124) ? A[cb + 4] : r.c.w;
    return r;
}
static __device__ __forceinline__ float4 westv(const S7& s) { return make_float4(s.wl, s.c.x, s.c.y, s.c.z); }
static __device__ __forceinline__ float4 eastv(const S7& s) { return make_float4(s.c.y, s.c.z, s.c.w, s.wr); }

static __device__ __forceinline__ float4 rcp4(float dt, float4 g) {
    return make_float4(1.f/(1.f+dt*g.x), 1.f/(1.f+dt*g.y), 1.f/(1.f+dt*g.z), 1.f/(1.f+dt*g.w));
}
static __device__ __forceinline__ void scale7(S7& u, const S7& f) {
    u.c = u.c * f.c; u.n = u.n * f.n; u.s = u.s * f.s; u.b = u.b * f.b; u.t = u.t * f.t;
    u.wl *= f.wl; u.wr *= f.wr;
}

#define IDX6(dd)                                      \
    const int d = (dd);                               \
    const int dB = cl(d - 1), dT = cl(d + 1);         \
    const int cb = ix(d, h, w4);                      \
    const int nb = ix(d, hN, w4), sb = ix(d, hS, w4); \
    const int bb = ix(dB, h, w4), tb = ix(dT, h, w4);

// ---------------------------------------------------------------------------
__global__ void __launch_bounds__(128) k_predictor(
    const float* __restrict__ U, const float* __restrict__ V, const float* __restrict__ W_,
    const float* __restrict__ P, const float* __restrict__ SG, const float* __restrict__ DT,
    float* __restrict__ BU, float* __restrict__ BV, float* __restrict__ BW)
{
    const int w4 = threadIdx.x << 2;
    const int h  = (blockIdx.y << 2) + threadIdx.y;
    const int hS = cl(h - 1), hN = cl(h + 1);
    IDX6(blockIdx.z);

    S7 g  = ld7(SG, cb, nb, sb, bb, tb, w4);
    S7 p  = ld7(P,  cb, nb, sb, bb, tb, w4);
    S7 su = ld7(U,  cb, nb, sb, bb, tb, w4);
    S7 sv = ld7(V,  cb, nb, sb, bb, tb, w4);
    S7 sw = ld7(W_, cb, nb, sb, bb, tb, w4);
    const float dt = DT[0];

    S7 f;
    f.c = rcp4(dt, g.c); f.n = rcp4(dt, g.n); f.s = rcp4(dt, g.s);
    f.b = rcp4(dt, g.b); f.t = rcp4(dt, g.t);
    f.wl = 1.f/(1.f+dt*g.wl); f.wr = 1.f/(1.f+dt*g.wr);

    scale7(su, f); scale7(sv, f); scale7(sw, f);
    const float4 uc = su.c, vc = sv.c, wc = sw.c;

    float4 gpx = 0.5f * (eastv(p) - westv(p));
    float4 gpy = 0.5f * (p.n - p.s);
    float4 gpz = 0.5f * (p.t - p.b);

    {
        float4 west = westv(su); if (w4 == 0) west.x = 1.0f;
        float4 east = eastv(su);
        float4 lap = west + east + su.n + su.s + su.b + su.t - 6.f * su.c;
        float4 ax = 0.5f * (east - west), ay = 0.5f * (su.n - su.s), az = 0.5f * (su.t - su.b);
        st4(BU, cb, (uc + 0.5f*dt*(lap - uc*ax - vc*ay - wc*az) - dt*gpx) * f.c);
    }
    {
        float4 west = westv(sv), east = eastv(sv);
        float4 lap = west + east + sv.n + sv.s + sv.b + sv.t - 6.f * sv.c;
        float4 ax = 0.5f * (east - west), ay = 0.5f * (sv.n - sv.s), az = 0.5f * (sv.t - sv.b);
        st4(BV, cb, (vc + 0.5f*dt*(lap - uc*ax - vc*ay - wc*az) - dt*gpy) * f.c);
    }
    {
        float4 west = westv(sw), east = eastv(sw);
        float4 lap = west + east + sw.n + sw.s + sw.b + sw.t - 6.f * sw.c;
        float4 ax = 0.5f * (east - west), ay = 0.5f * (sw.n - sw.s), az = 0.5f * (sw.t - sw.b);
        st4(BW, cb, (wc + 0.5f*dt*(lap - uc*ax - vc*ay - wc*az) - dt*gpz) * f.c);
    }
}

// ---------------------------------------------------------------------------
__global__ void __launch_bounds__(128) k_corrector(
    const float* __restrict__ BU, const float* __restrict__ BV, const float* __restrict__ BW,
    const float* __restrict__ U, const float* __restrict__ V, const float* __restrict__ W_,
    const float* __restrict__ P, const float* __restrict__ SG, const float* __restrict__ DT,
    float* __restrict__ U1, float* __restrict__ V1, float* __restrict__ W1)
{
    const int w4 = threadIdx.x << 2;
    const int h  = (blockIdx.y << 2) + threadIdx.y;
    const int hS = cl(h - 1), hN = cl(h + 1);
    IDX6(blockIdx.z);

    const float4 sg = ld4(SG, cb);
    const float4 Uc = ld4(U, cb), Vc = ld4(V, cb), Wc = ld4(W_, cb);
    S7 p = ld7(P,  cb, nb, sb, bb, tb, w4);
    S7 a = ld7(BU, cb, nb, sb, bb, tb, w4);
    S7 b = ld7(BV, cb, nb, sb, bb, tb, w4);
    S7 c = ld7(BW, cb, nb, sb, bb, tb, w4);
    const float dt = DT[0];

    const float4 fc = rcp4(dt, sg);
    const float4 uc = Uc * fc, vc = Vc * fc, wc = Wc * fc;
    const float4 buc = a.c, bvc = b.c, bwc = c.c;

    float4 gpx = 0.5f * (eastv(p) - westv(p));
    float4 gpy = 0.5f * (p.n - p.s);
    float4 gpz = 0.5f * (p.t - p.b);

    {
        float4 west = westv(a); if (w4 == 0) west.x = 1.0f;
        float4 east = eastv(a);
        float4 lap = west + east + a.n + a.s + a.b + a.t - 6.f * a.c;
        float4 ax = 0.5f * (east - west), ay = 0.5f * (a.n - a.s), az = 0.5f * (a.t - a.b);
        st4(U1, cb, (uc + dt*(lap - buc*ax - bvc*ay - bwc*az) - dt*gpx) * fc);
    }
    {
        float4 west = westv(b), east = eastv(b);
        float4 lap = west + east + b.n + b.s + b.b + b.t - 6.f * b.c;
        float4 ax = 0.5f * (east - west), ay = 0.5f * (b.n - b.s), az = 0.5f * (b.t - b.b);
        st4(V1, cb, (vc + dt*(lap - buc*ax - bvc*ay - bwc*az) - dt*gpy) * fc);
    }
    {
        float4 west = westv(c), east = eastv(c);
        float4 lap = west + east + c.n + c.s + c.b + c.t - 6.f * c.c;
        float4 ax = 0.5f * (east - west), ay = 0.5f * (c.n - c.s), az = 0.5f * (c.t - c.b);
        st4(W1, cb, (wc + dt*(lap - buc*ax - bvc*ay - bwc*az) - dt*gpz) * fc);
    }
}

// ---------------------------------------------------------------------------
// Shared tail for both residual kernels: c64buf -> Rp2 store + 16^3 partial.
// Block covers d32 = blockIdx.z, h32 in {2y, 2y+1}, all w32.
// Writes its half-sum for 16^3 cell into Rp3[(z&1)*4096 + idx].
// ---------------------------------------------------------------------------
static __device__ __forceinline__ void resid_tail(
    float c64buf[2][4][64], float c32buf[64],
    float* __restrict__ Rp2, float* __restrict__ Rp3, int tid)
{
    if (tid < 64) {
        int wc2 = tid & 31, hc2 = tid >> 5;
        float s = 0.f;
        #pragma unroll
        for (int dc = 0; dc < 2; ++dc)
            #pragma unroll
            for (int hh = 0; hh < 2; ++hh)
                s += c64buf[dc][hc2 * 2 + hh][wc2 * 2] + c64buf[dc][hc2 * 2 + hh][wc2 * 2 + 1];
        float v = 0.125f * s;
        c32buf[hc2 * 32 + wc2] = v;
        Rp2[((blockIdx.z) * 32 + (blockIdx.y << 1) + hc2) * 32 + wc2] = v;
    }
    __syncthreads();
    if (tid < 16) {
        // 16^3 partial: d16 = z>>1, h16 = y, w16 = tid; half-sum over h32loc, wpair
        float s = c32buf[tid * 2] + c32buf[tid * 2 + 1]
                + c32buf[32 + tid * 2] + c32buf[32 + tid * 2 + 1];
        int idx = (((int)blockIdx.z >> 1) * 16 + (int)blockIdx.y) * 16 + tid;
        Rp3[(blockIdx.z & 1) * 4096 + idx] = 0.125f * s;
    }
}

// ---------------------------------------------------------------------------
// Iter-0 fused: div + residual + Ppre(=p - r0/diag) + 128->64 + 64->32 + 16^3 partial.
// Block covers 4 d-planes (2 pair-passes), h:8, w:128. Grid (1,16,32).
// ---------------------------------------------------------------------------
__global__ void __launch_bounds__(256) k_residdiv(
    const float* __restrict__ P, const float* __restrict__ U1,
    const float* __restrict__ V1, const float* __restrict__ W1,
    const float* __restrict__ DT,
    float* __restrict__ B, float* __restrict__ PP,
    float* __restrict__ Rp1, float* __restrict__ Rp2, float* __restrict__ Rp3)
{
    __shared__ float sred[8][64];
    __shared__ float c64buf[2][4][64];
    __shared__ float c32buf[64];
    const int w4 = threadIdx.x << 2;
    const int h  = (blockIdx.y << 3) + threadIdx.y;
    const int hS = cl(h - 1), hN = cl(h + 1);
    const int tid = threadIdx.y * 32 + threadIdx.x;
    const float dt = DT[0];
    const float rdt = -1.f / dt;

    #pragma unroll
    for (int pair = 0; pair < 2; ++pair) {
        S7 pp[2]; float4 u1c[2], vn[2], vs[2], wb[2], wt[2];
        float uwl[2], uwr[2]; int cbs[2];
        #pragma unroll
        for (int d2 = 0; d2 < 2; ++d2) {
            IDX6((blockIdx.z << 2) + (pair << 1) + d2);
            cbs[d2] = cb;
            pp[d2]  = ld7(P, cb, nb, sb, bb, tb, w4);
            u1c[d2] = ld4(U1, cb);
            uwl[d2] = (w4 > 0)   ? U1[cb - 1] : u1c[d2].x;
            uwr[d2] = (w4 < 124) ? U1[cb + 4] : u1c[d2].w;
            vn[d2] = ld4(V1, nb); vs[d2] = ld4(V1, sb);
            wt[d2] = ld4(W1, tb); wb[d2] = ld4(W1, bb);
        }
        float acc0 = 0.f, acc1 = 0.f;
        #pragma unroll
        for (int d2 = 0; d2 < 2; ++d2) {
            float wl = uwl[d2]; if (w4 == 0) wl = 1.0f;
            float4 west = make_float4(wl, u1c[d2].x, u1c[d2].y, u1c[d2].z);
            float4 east = make_float4(u1c[d2].y, u1c[d2].z, u1c[d2].w, uwr[d2]);
            float4 b4 = rdt * (0.5f*(east - west) + 0.5f*(vn[d2] - vs[d2]) + 0.5f*(wt[d2] - wb[d2]));
            st4(B, cbs[d2], b4);

            float4 pw = westv(pp[d2]), pe = eastv(pp[d2]);
            float4 lap = pw + pe + pp[d2].n + pp[d2].s + pp[d2].b + pp[d2].t - 6.f * pp[d2].c;
            float4 rr = lap - b4;
            st4(PP, cbs[d2], pp[d2].c - make_float4(rr.x/(-6.f), rr.y/(-6.f), rr.z/(-6.f), rr.w/(-6.f)));
            acc0 += rr.x + rr.y;
            acc1 += rr.z + rr.w;
        }
        sred[threadIdx.y][threadIdx.x * 2]     = acc0;
        sred[threadIdx.y][threadIdx.x * 2 + 1] = acc1;
        __syncthreads();
        {
            int cw = tid & 63, chh = tid >> 6;
            float v = 0.125f * (sred[2 * chh][cw] + sred[2 * chh + 1][cw]);
            int dc = (blockIdx.z << 1) + pair, hc = (blockIdx.y << 2) + chh;
            Rp1[(dc * 64 + hc) * 64 + cw] = v;
            c64buf[pair][chh][cw] = v;
        }
        __syncthreads();
    }
    resid_tail(c64buf, c32buf, Rp2, Rp3, tid);
}

// ---------------------------------------------------------------------------
// Iter-1 residual: Ppre = p - (lap(p)-B)/diag, + restrictions + 16^3 partial.
// ---------------------------------------------------------------------------
__global__ void __launch_bounds__(256) k_resid(
    const float* __restrict__ P, const float* __restrict__ B,
    float* __restrict__ PP, float* __restrict__ Rp1,
    float* __restrict__ Rp2, float* __restrict__ Rp3)
{
    __shared__ float sred[8][64];
    __shared__ float c64buf[2][4][64];
    __shared__ float c32buf[64];
    const int w4 = threadIdx.x << 2;
    const int h  = (blockIdx.y << 3) + threadIdx.y;
    const int hS = cl(h - 1), hN = cl(h + 1);
    const int tid = threadIdx.y * 32 + threadIdx.x;

    #pragma unroll
    for (int pair = 0; pair < 2; ++pair) {
        S7 pp[2]; float4 bc[2]; int cbs[2];
        #pragma unroll
        for (int d2 = 0; d2 < 2; ++d2) {
            IDX6((blockIdx.z << 2) + (pair << 1) + d2);
            cbs[d2] = cb;
            pp[d2] = ld7(P, cb, nb, sb, bb, tb, w4);
            bc[d2] = ld4(B, cb);
        }
        float acc0 = 0.f, acc1 = 0.f;
        #pragma unroll
        for (int d2 = 0; d2 < 2; ++d2) {
            float4 pw = westv(pp[d2]), pe = eastv(pp[d2]);
            float4 lap = pw + pe + pp[d2].n + pp[d2].s + pp[d2].b + pp[d2].t - 6.f * pp[d2].c;
            float4 rr = lap - bc[d2];
            st4(PP, cbs[d2], pp[d2].c - make_float4(rr.x/(-6.f), rr.y/(-6.f), rr.z/(-6.f), rr.w/(-6.f)));
            acc0 += rr.x + rr.y;
            acc1 += rr.z + rr.w;
        }
        sred[threadIdx.y][threadIdx.x * 2]     = acc0;
        sred[threadIdx.y][threadIdx.x * 2 + 1] = acc1;
        __syncthreads();
        {
            int cw = tid & 63, chh = tid >> 6;
            float v = 0.125f * (sred[2 * chh][cw] + sred[2 * chh + 1][cw]);
            int dc = (blockIdx.z << 1) + pair, hc = (blockIdx.y << 2) + chh;
            Rp1[(dc * 64 + hc) * 64 + cw] = v;
            c64buf[pair][chh][cw] = v;
        }
        __syncthreads();
    }
    resid_tail(c64buf, c32buf, Rp2, Rp3, tid);
}

static __device__ __forceinline__ float mgcell(const float* __restrict__ Wp, int mc,
                                               float r, int d, int h, int w, int m)
{
    auto g = [&](int dd, int hh, int ww) -> float {
        if (dd < 0 || dd >= m || hh < 0 || hh >= m || ww < 0 || ww >= m) return 0.f;
        return Wp[((dd >> 1) * mc + (hh >> 1)) * mc + (ww >> 1)];
    };
    float wc = g(d, h, w);
    float lap = g(d-1,h,w) + g(d+1,h,w) + g(d,h-1,w) + g(d,h+1,w) + g(d,h,w-1) + g(d,h,w+1) - 6.f * wc;
    return wc - lap / (-6.f) + r / (-6.f);
}

// padded-coarse read: fine index in [-1, m] maps to ((f>>1)+1)
static __device__ __forceinline__ float gpad(const float* __restrict__ W, int p1, int p2,
                                             int dd, int hh, int ww)
{
    return W[((dd >> 1) + 1) * p1 + ((hh >> 1) + 1) * p2 + ((ww >> 1) + 1)];
}
static __device__ __forceinline__ float mgpad(const float* __restrict__ W, int p1, int p2,
                                              float r, int d, int h, int w)
{
    float wc = gpad(W, p1, p2, d, h, w);
    float lap = gpad(W, p1, p2, d-1, h, w) + gpad(W, p1, p2, d+1, h, w)
              + gpad(W, p1, p2, d, h-1, w) + gpad(W, p1, p2, d, h+1, w)
              + gpad(W, p1, p2, d, h, w-1) + gpad(W, p1, p2, d, h, w+1) - 6.f * wc;
    return wc - lap / (-6.f) + r / (-6.f);
}

// ---------------------------------------------------------------------------
// Single-block coarse solver (1024 thr): R16 = Rp3[0]+Rp3[1] (32 KB), pyramid
// down to 1, solve back up to W16. Zero-padded smem => branch-free mgcells.
// ---------------------------------------------------------------------------
__global__ void __launch_bounds__(1024) k_coarse16(
    const float* __restrict__ Rp3, float* __restrict__ W16g, float* __restrict__ o_r)
{
    __shared__ float R16[4096], R8[512], R4[64], R2[8];
    __shared__ float W8p[1000], W4p[216], W2p[64], W1p[27];
    const int tid = threadIdx.x;

    if (tid < 1000) W8p[tid] = 0.f;
    if (tid < 216) W4p[tid] = 0.f;
    if (tid >= 256 && tid < 320) W2p[tid - 256] = 0.f;
    if (tid >= 512 && tid < 539) W1p[tid - 512] = 0.f;

    {   // combine the two block-halves: R16 = Rp3[0] + Rp3[1]
        const int k4 = tid << 2;
        float4 a = ld4(Rp3, k4);
        float4 b = ld4(Rp3, 4096 + k4);
        *reinterpret_cast<float4*>(R16 + k4) = a + b;
    }
    __syncthreads();
    if (tid < 512) {   // 16 -> 8
        int w = tid & 7, h = (tid >> 3) & 7, d = tid >> 6;
        int b0 = ((2 * d) * 16 + 2 * h) * 16 + 2 * w;
        R8[tid] = 0.125f * (R16[b0] + R16[b0+1] + R16[b0+16] + R16[b0+17]
                          + R16[b0+256] + R16[b0+257] + R16[b0+272] + R16[b0+273]);
    }
    __syncthreads();
    if (tid < 64) {    // 8 -> 4
        int w = tid & 3, h = (tid >> 2) & 3, d = tid >> 4;
        int b0 = ((2 * d) * 8 + 2 * h) * 8 + 2 * w;
        R4[tid] = 0.125f * (R8[b0] + R8[b0+1] + R8[b0+8] + R8[b0+9]
                          + R8[b0+64] + R8[b0+65] + R8[b0+72] + R8[b0+73]);
    }
    __syncthreads();
    if (tid < 8) {     // 4 -> 2
        int w = tid & 1, h = (tid >> 1) & 1, d = tid >> 2;
        int b0 = ((2 * d) * 4 + 2 * h) * 4 + 2 * w;
        R2[tid] = 0.125f * (R4[b0] + R4[b0+1] + R4[b0+4] + R4[b0+5]
                          + R4[b0+16] + R4[b0+17] + R4[b0+20] + R4[b0+21]);
    }
    __syncthreads();
    if (tid == 0) {    // 2 -> 1 + coarsest solve; W1p center = (1,1,1)
        float r1 = 0.125f * (R2[0]+R2[1]+R2[2]+R2[3]+R2[4]+R2[5]+R2[6]+R2[7]);
        W1p[13] = r1 / (-6.f);
        if (o_r) o_r[0] = r1;
    }
    __syncthreads();
    if (tid < 8) {     // m = 2 -> W2p (4^3, pitches 16,4)
        int w = tid & 1, h = (tid >> 1) & 1, d = tid >> 2;
        W2p[(d+1)*16 + (h+1)*4 + (w+1)] = mgpad(W1p, 9, 3, R2[tid], d, h, w);
    }
    __syncthreads();
    if (tid < 64) {    // m = 4 -> W4p (6^3, pitches 36,6)
        int w = tid & 3, h = (tid >> 2) & 3, d = tid >> 4;
        W4p[(d+1)*36 + (h+1)*6 + (w+1)] = mgpad(W2p, 16, 4, R4[tid], d, h, w);
    }
    __syncthreads();
    if (tid < 512) {   // m = 8 -> W8p (10^3, pitches 100,10)
        int w = tid & 7, h = (tid >> 3) & 7, d = tid >> 6;
        W8p[(d+1)*100 + (h+1)*10 + (w+1)] = mgpad(W4p, 36, 6, R8[tid], d, h, w);
    }
    __syncthreads();
    #pragma unroll
    for (int k = tid; k < 4096; k += 1024) {   // m = 16 -> global
        int w = k & 15, h = (k >> 4) & 15, d = k >> 8;
        W16g[k] = mgpad(W8p, 100, 10, R16[k], d, h, w);
    }
}

// m=32 MG level, grid-wide (W16 tiny and cache-hot)
__global__ void __launch_bounds__(256) k_mg32(
    const float* __restrict__ W16, const float* __restrict__ Rp2, float* __restrict__ W32)
{
    const int t = blockIdx.x * 256 + threadIdx.x;   // 32768
    const int w = t & 31, h = (t >> 5) & 31, d = t >> 10;
    W32[t] = mgcell(W16, 16, Rp2[t], d, h, w, 32);
}

// ---------------------------------------------------------------------------
// In-place p-update with m=64 MG level fused: Pio -= mg64(W32, Rp1)
// ---------------------------------------------------------------------------
__global__ void __launch_bounds__(256) k_pupdate(
    float* __restrict__ Pio, const float* __restrict__ W32,
    const float* __restrict__ Rp1, float* __restrict__ wmg_out)
{
    const int w4 = threadIdx.x << 2;
    const int h  = (blockIdx.y << 3) + threadIdx.y;
    const int d  = blockIdx.z;
    const int cb = ix(d, h, w4);

    const int d64 = d >> 1, h64 = h >> 1, cw0 = w4 >> 1;
    const int crow = (d64 * 64 + h64) * 64 + cw0;
    const float r64_0 = Rp1[crow], r64_1 = Rp1[crow + 1];
    const float4 po = ld4(Pio, cb);

    const float mg0 = mgcell(W32, 32, r64_0, d64, h64, cw0,     64);
    const float mg1 = mgcell(W32, 32, r64_1, d64, h64, cw0 + 1, 64);
    const float4 wv = make_float4(mg0, mg0, mg1, mg1);
    st4(Pio, cb, po - wv);
    if (wmg_out) st4(wmg_out, cb, wv);
}

// ---------------------------------------------------------------------------
__global__ void __launch_bounds__(256) k_final(
    const float* __restrict__ U1, const float* __restrict__ V1, const float* __restrict__ W1,
    const float* __restrict__ Pf, const float* __restrict__ SG, const float* __restrict__ DT,
    float* __restrict__ OU, float* __restrict__ OV, float* __restrict__ OW)
{
    const int w4 = threadIdx.x << 2;
    const int h  = (blockIdx.y << 3) + threadIdx.y;
    const int hS = cl(h - 1), hN = cl(h + 1);
    IDX6(blockIdx.z);

    S7 p = ld7(Pf, cb, nb, sb, bb, tb, w4);
    const float4 sg = ld4(SG, cb);
    const float4 u1 = ld4(U1, cb), v1 = ld4(V1, cb), w1 = ld4(W1, cb);
    const float dt = DT[0];

    const float4 fc = rcp4(dt, sg);
    float4 gpx = 0.5f * (eastv(p) - westv(p));
    float4 gpy = 0.5f * (p.n - p.s);
    float4 gpz = 0.5f * (p.t - p.b);
    st4(OU, cb, (u1 - dt * gpx) * fc);
    st4(OV, cb, (v1 - dt * gpy) * fc);
    st4(OW, cb, (w1 - dt * gpz) * fc);
}

// ---------------------------------------------------------------------------
extern "C" void kernel_launch(void* const* d_in, const int* in_sizes, int n_in,
                              void* d_out, int out_size)
{
    const float* U  = (const float*)d_in[0];
    const float* V  = (const float*)d_in[1];
    const float* W_ = (const float*)d_in[2];
    const float* P  = (const float*)d_in[3];
    const float* SG = (const float*)d_in[4];
    const float* DT = (const float*)d_in[5];

    float* out   = (float*)d_out;
    float* o_u   = out;
    float* o_v   = out + (size_t)N3;
    float* o_w   = out + 2 * (size_t)N3;
    float* o_p   = out + 3 * (size_t)N3;
    float* o_wmg = out + 4 * (size_t)N3;
    float* o_r   = out + 5 * (size_t)N3;

    float* S = nullptr;
    cudaGetSymbolAddress((void**)&S, g_scratch);
    float* BU = S;
    float* BV = S + (size_t)N3;
    float* BW = S + 2 * (size_t)N3;
    float* U1 = S + 3 * (size_t)N3;
    float* V1 = S + 4 * (size_t)N3;
    float* W1 = S + 5 * (size_t)N3;
    float* B  = S + 6 * (size_t)N3;
    float* P1 = S + 7 * (size_t)N3;
    float* Rp1 = S + 8 * (size_t)N3;     // 64^3
    float* Rp2 = Rp1 + 262144;           // 32^3
    float* W32 = Rp2 + 32768;            // 32^3
    float* W16 = W32 + 32768;            // 16^3
    float* Rp3 = W16 + 4096;             // 2 x 16^3 split partials

    dim3 blkF(32, 4), grdF(1, 32, 128);     // fat kernels, 128 thr
    dim3 blkR(32, 8), grdR(1, 16, 32);      // residual (4 planes/block)
    dim3 grdP(1, 16, 128);                  // full-depth grids with blkR

    k_predictor<<<grdF, blkF>>>(U, V, W_, P, SG, DT, BU, BV, BW);
    k_corrector<<<grdF, blkF>>>(BU, BV, BW, U, V, W_, P, SG, DT, U1, V1, W1);

    // iteration 0: Ppre -> P1, then P1 -= wmg (in place)
    k_residdiv<<<grdR, blkR>>>(P, U1, V1, W1, DT, B, P1, Rp1, Rp2, Rp3);
    k_coarse16<<<1, 1024>>>(Rp3, W16, nullptr);
    k_mg32<<<128, 256>>>(W16, Rp2, W32);
    k_pupdate<<<grdP, blkR>>>(P1, W32, Rp1, nullptr);

    // iteration 1: Ppre -> o_p, then o_p -= wmg (in place) + o_wmg
    k_resid<<<grdR, blkR>>>(P1, B, o_p, Rp1, Rp2, Rp3);
    k_coarse16<<<1, 1024>>>(Rp3, W16, o_r);
    k_mg32<<<128, 256>>>(W16, Rp2, W32);
    k_pupdate<<<grdP, blkR>>>(o_p, W32, Rp1, o_wmg);

    k_final<<<grdP, blkR>>>(U1, V1, W1, o_p, SG, DT, o_u, o_v, o_w);
}